// round 10
// baseline (speedup 1.0000x reference)
#include <cuda_runtime.h>
#include <cstdint>

#define BB   4
#define TT   2048
#define DD   1024
#define HH   8
#define DHH  64
#define EE   5
#define BT   (BB*TT)     // 8192
#define HD   (HH*DHH)    // 512
#define NPROJ 1408       // [q 512 | k 512 | xv 320 | pad 64]
#define NGATE 128        // [glv 40 | glo 40 | pad 48]
#define C_Q   0
#define C_K   512
#define C_XV  1024
#define G_GLV 0
#define G_GLO 40
#define GATE_NSPLIT 8
#define GATE_KCHUNK (DD/GATE_NSPLIT)   // 128

// ---------------- scratch (device globals; no allocations allowed) ----------
__device__ float g_xt  [BT*DD];                 // x pre-rounded to tf32
__device__ float g_Bbig[DD*NPROJ];              // packed [Wq|Wk|Wv|0] tf32
__device__ float g_Bg  [DD*NGATE];              // packed [Ws|Wd|0] fp32 (3x path)
__device__ float g_WoT [EE*DHH*DD];             // Wo pre-rounded to tf32
__device__ float g_proj[BT*NPROJ];
__device__ float g_glgp[GATE_NSPLIT*BT*NGATE];  // split-K partials
__device__ float g_glg [BT*NGATE];
__device__ float g_v   [BT*HD];
__device__ float g_at  [BT*HD];
__device__ float g_agg [BT*EE*DHH];             // tf32-rounded by out_gate

// ---------------- helpers ----------------------------------------------------
__device__ __forceinline__ uint32_t f2tf32(float x) {
    uint32_t r;
    asm("cvt.rna.tf32.f32 %0, %1;" : "=r"(r) : "f"(x));
    return r;
}
__device__ __forceinline__ void tf32_split(float x, uint32_t& hi, uint32_t& lo) {
    hi = f2tf32(x);
    lo = f2tf32(x - __uint_as_float(hi));
}
__device__ __forceinline__ float ex2(float x) {
    float r; asm("ex2.approx.ftz.f32 %0, %1;" : "=f"(r) : "f"(x)); return r;
}
__device__ __forceinline__ void cp_async16(uint32_t s, const void* g) {
    asm volatile("cp.async.cg.shared.global [%0], [%1], 16;" :: "r"(s), "l"(g));
}
__device__ __forceinline__ void cp_commit() { asm volatile("cp.async.commit_group;"); }
__device__ __forceinline__ void cp_wait0()  { asm volatile("cp.async.wait_group 0;"); }
__device__ __forceinline__ void cp_wait1()  { asm volatile("cp.async.wait_group 1;"); }
__device__ __forceinline__ void mma_tf32(float* c, const uint32_t* a, const uint32_t* b) {
    asm volatile(
        "mma.sync.aligned.m16n8k8.row.col.f32.tf32.tf32.f32 "
        "{%0,%1,%2,%3}, {%4,%5,%6,%7}, {%8,%9}, {%0,%1,%2,%3};"
        : "+f"(c[0]), "+f"(c[1]), "+f"(c[2]), "+f"(c[3])
        : "r"(a[0]), "r"(a[1]), "r"(a[2]), "r"(a[3]), "r"(b[0]), "r"(b[1]));
}

// ---------------- fused pack kernel ------------------------------------------
#define PK_N1 (BT*DD/4)
#define PK_N2 (PK_N1 + DD*NPROJ)
#define PK_N3 (PK_N2 + DD*NGATE)
#define PK_N4 (PK_N3 + EE*DHH*DD)

__global__ void pack_all_kernel(
    const float4* __restrict__ x,  uint4* __restrict__ xt,
    const float* __restrict__ Wq, const float* __restrict__ Wk,
    const float* __restrict__ Wv, uint32_t* __restrict__ Bb,
    const float* __restrict__ Ws, const float* __restrict__ Wd,
    float* __restrict__ Bg,
    const float* __restrict__ Wo, uint32_t* __restrict__ WoT)
{
    int idx = blockIdx.x * 256 + threadIdx.x;
    if (idx < PK_N1) {
        float4 v = x[idx];
        uint4 o;
        o.x = f2tf32(v.x); o.y = f2tf32(v.y); o.z = f2tf32(v.z); o.w = f2tf32(v.w);
        xt[idx] = o;
    } else if (idx < PK_N2) {
        int i = idx - PK_N1;
        int d = i / NPROJ, c = i % NPROJ;
        float v = 0.f;
        if      (c < 512)  v = Wq[d * 512 + c];
        else if (c < 1024) v = Wk[d * 512 + c - 512];
        else if (c < 1344) {
            int cc = c - 1024;
            int e = cc >> 6, kk = cc & 63;
            v = Wv[((size_t)e * DD + d) * 64 + kk];
        }
        Bb[i] = f2tf32(v);
    } else if (idx < PK_N3) {
        int i = idx - PK_N2;
        int d = i / NGATE, c = i % NGATE;
        float v = 0.f;
        if      (c < 40) v = Ws[d * 40 + c];
        else if (c < 80) v = Wd[d * 40 + c - 40];
        Bg[i] = v;
    } else if (idx < PK_N4) {
        int i = idx - PK_N3;
        WoT[i] = f2tf32(Wo[i]);
    }
}

// ---------------- tf32 tensor-core GEMM (SPLIT: 0=raw-bits, 3=3x) -----------
#define SA_STRIDE 36
#define SB_STRIDE 136
#define SA_FLOATS (128*SA_STRIDE)
#define SB_FLOATS (32*SB_STRIDE)
#define GEMM_SMEM_BYTES ((2*SA_FLOATS + 2*SB_FLOATS)*4)  // 71680

template<int SPLIT, bool ROUND>
__global__ __launch_bounds__(256) void tf32_gemm_kernel(
    const float* __restrict__ A, const float* __restrict__ B, float* __restrict__ C,
    int M, int N, int K, int lda, int ldb, int ldc, int ksplit, size_t csplit)
{
    extern __shared__ float smem[];
    float* sA = smem;
    float* sB = smem + 2 * SA_FLOATS;

    {
        const int z = blockIdx.z;
        const int kbeg = z * ksplit;
        A += kbeg;
        B += (size_t)kbeg * ldb;
        C += (size_t)z * csplit;
    }

    const int tid  = threadIdx.x;
    const int warp = tid >> 5, lane = tid & 31;
    const int lq = lane >> 2, lr = lane & 3;
    const int wm = (warp & 1) * 64;
    const int wn = (warp >> 1) * 32;
    const int bm = blockIdx.y * 128;
    const int bn = blockIdx.x * 128;

    float acc[4][4][4];
#pragma unroll
    for (int i = 0; i < 4; i++)
#pragma unroll
        for (int j = 0; j < 4; j++)
#pragma unroll
            for (int v = 0; v < 4; v++) acc[i][j][v] = 0.f;

    const uint32_t sA_base = (uint32_t)__cvta_generic_to_shared(sA);
    const uint32_t sB_base = (uint32_t)__cvta_generic_to_shared(sB);

#define COPY_STAGE(buf, k0)                                                     \
    {                                                                           \
        _Pragma("unroll")                                                       \
        for (int it = 0; it < 4; it++) {                                        \
            int f = tid + it * 256;                                             \
            int ar = f >> 3, ac4 = f & 7;                                       \
            cp_async16(sA_base + ((buf) * SA_FLOATS + ar * SA_STRIDE + ac4 * 4) * 4, \
                       A + (size_t)(bm + ar) * lda + (k0) + ac4 * 4);           \
            int br = f >> 5, bc4 = f & 31;                                      \
            cp_async16(sB_base + ((buf) * SB_FLOATS + br * SB_STRIDE + bc4 * 4) * 4, \
                       B + (size_t)((k0) + br) * ldb + bn + bc4 * 4);           \
        }                                                                       \
    }

    const int nk = K >> 5;
    COPY_STAGE(0, 0);
    cp_commit();

    for (int kt = 0; kt < nk; kt++) {
        if (kt + 1 < nk) {
            COPY_STAGE((kt + 1) & 1, (kt + 1) << 5);
            cp_commit();
            cp_wait1();
        } else {
            cp_wait0();
        }
        __syncthreads();

        const float* cA = sA + (kt & 1) * SA_FLOATS;
        const float* cB = sB + (kt & 1) * SB_FLOATS;
#pragma unroll
        for (int s = 0; s < 4; s++) {
            uint32_t ah[4][4], al[4][4], bh[4][2], bl[4][2];
#pragma unroll
            for (int i = 0; i < 4; i++) {
                int base = (wm + i * 16 + lq) * SA_STRIDE + s * 8 + lr;
                if (SPLIT == 3) {
                    tf32_split(cA[base],                  ah[i][0], al[i][0]);
                    tf32_split(cA[base + 8 * SA_STRIDE],  ah[i][1], al[i][1]);
                    tf32_split(cA[base + 4],              ah[i][2], al[i][2]);
                    tf32_split(cA[base + 8*SA_STRIDE+4],  ah[i][3], al[i][3]);
                } else {            // SPLIT == 0: operands pre-rounded to tf32
                    ah[i][0] = __float_as_uint(cA[base]);
                    ah[i][1] = __float_as_uint(cA[base + 8 * SA_STRIDE]);
                    ah[i][2] = __float_as_uint(cA[base + 4]);
                    ah[i][3] = __float_as_uint(cA[base + 8*SA_STRIDE+4]);
                }
            }
#pragma unroll
            for (int j = 0; j < 4; j++) {
                int base = (s * 8 + lr) * SB_STRIDE + wn + j * 8 + lq;
                if (SPLIT == 3) {
                    tf32_split(cB[base],                  bh[j][0], bl[j][0]);
                    tf32_split(cB[base + 4 * SB_STRIDE],  bh[j][1], bl[j][1]);
                } else {
                    bh[j][0] = __float_as_uint(cB[base]);
                    bh[j][1] = __float_as_uint(cB[base + 4 * SB_STRIDE]);
                }
            }
#pragma unroll
            for (int i = 0; i < 4; i++)
#pragma unroll
                for (int j = 0; j < 4; j++) {
                    if (SPLIT == 3) {
                        mma_tf32(acc[i][j], ah[i], bl[j]);
                        mma_tf32(acc[i][j], al[i], bh[j]);
                    }
                    mma_tf32(acc[i][j], ah[i], bh[j]);
                }
        }
        __syncthreads();
    }
#undef COPY_STAGE

#pragma unroll
    for (int i = 0; i < 4; i++) {
        int r0 = bm + wm + i * 16 + lq;
#pragma unroll
        for (int j = 0; j < 4; j++) {
            int c0 = bn + wn + j * 8 + 2 * lr;
            float v0, v1, v2, v3;
            if (ROUND) {
                v0 = __uint_as_float(f2tf32(acc[i][j][0]));
                v1 = __uint_as_float(f2tf32(acc[i][j][1]));
                v2 = __uint_as_float(f2tf32(acc[i][j][2]));
                v3 = __uint_as_float(f2tf32(acc[i][j][3]));
            } else {
                v0 = acc[i][j][0]; v1 = acc[i][j][1];
                v2 = acc[i][j][2]; v3 = acc[i][j][3];
            }
            *(float2*)&C[(size_t)r0 * ldc + c0]       = make_float2(v0, v1);
            *(float2*)&C[(size_t)(r0 + 8) * ldc + c0] = make_float2(v2, v3);
        }
    }
}

// ---------------- split-K reduce (fixed order -> deterministic) --------------
__global__ void gate_reduce_kernel(const float4* __restrict__ part, float4* __restrict__ out) {
    int i = blockIdx.x * 256 + threadIdx.x;
    if (i >= BT * NGATE / 4) return;
    const int stride = BT * NGATE / 4;
    float4 r = part[i];
#pragma unroll
    for (int p = 1; p < GATE_NSPLIT; p++) {
        float4 a = part[i + p * stride];
        r.x += a.x; r.y += a.y; r.z += a.z; r.w += a.w;
    }
    out[i] = r;
}

// ---------------- top-2 helper ----------------------------------------------
__device__ __forceinline__ void top2_of5(const float g[5], int& i1, int& i2) {
    i1 = 0;
#pragma unroll
    for (int e = 1; e < 5; e++) if (g[e] > g[i1]) i1 = e;
    i2 = (i1 == 0) ? 1 : 0;
#pragma unroll
    for (int e = 0; e < 5; e++) if (e != i1 && g[e] > g[i2]) i2 = e;
}

// ---------------- fused V combine (warp per token) ---------------------------
__global__ __launch_bounds__(256) void v_combine_kernel(
    const float* __restrict__ glg, const float* __restrict__ proj, float* __restrict__ v)
{
    const int bt   = blockIdx.x * 8 + (threadIdx.x >> 5);
    const int lane = threadIdx.x & 31;
    const float* g  = glg + (size_t)bt * NGATE + G_GLV;
    const float* xv = proj + (size_t)bt * NPROJ + C_XV;
    float* vr = v + (size_t)bt * HD;
#pragma unroll
    for (int h = 0; h < HH; h++) {
        float ga[5] = { g[h*5+0], g[h*5+1], g[h*5+2], g[h*5+3], g[h*5+4] };
        int i1, i2;
        top2_of5(ga, i1, i2);
        float w1 = 1.f / (1.f + __expf(-ga[i1]));
        float w2 = 1.f / (1.f + __expf(-ga[i2]));
        float2 x1 = *(const float2*)&xv[i1 * DHH + 2 * lane];
        float2 x2 = *(const float2*)&xv[i2 * DHH + 2 * lane];
        float2 r;
        r.x = __uint_as_float(f2tf32(w1 * x1.x + w2 * x2.x));
        r.y = __uint_as_float(f2tf32(w1 * x1.y + w2 * x2.y));
        *(float2*)&vr[h * DHH + 2 * lane] = r;
    }
}

// ---------------- tensor-core flash attention (R8 config: KV tile 64) --------
#define KSTRIDE 68
#define VSTRIDE 72
#define FL_SMEM ((2*64*KSTRIDE + 2*64*VSTRIDE)*4)   // 71680

__global__ __launch_bounds__(256) void flash_attn_tc_kernel(
    const float* __restrict__ proj, const float* __restrict__ v, float* __restrict__ attn)
{
    extern __shared__ float fsm[];
    float* sK = fsm;
    float* sV = fsm + 2*64*KSTRIDE;
    const int tid  = threadIdx.x;
    const int warp = tid >> 5, lane = tid & 31;
    const int lq = lane >> 2, lr = lane & 3;
    const int h = blockIdx.y & 7, b = blockIdx.y >> 3;
    const int qbase = blockIdx.x * 128 + warp * 16;

    const uint32_t sKu = (uint32_t)__cvta_generic_to_shared(sK);
    const uint32_t sVu = (uint32_t)__cvta_generic_to_shared(sV);

    const float QS = 0.1803368801f;   // 0.125 * log2(e)
    uint32_t qa[8][4];
    {
        const float* pa = proj + (size_t)(b*TT + qbase + lq) * NPROJ + C_Q + h*64;
        const float* pb = pa + (size_t)8 * NPROJ;
#pragma unroll
        for (int kc = 0; kc < 8; kc++) {
            qa[kc][0] = f2tf32(QS * pa[kc*8 + lr]);
            qa[kc][1] = f2tf32(QS * pb[kc*8 + lr]);
            qa[kc][2] = f2tf32(QS * pa[kc*8 + lr + 4]);
            qa[kc][3] = f2tf32(QS * pb[kc*8 + lr + 4]);
        }
    }

    float o[8][4];
#pragma unroll
    for (int nt = 0; nt < 8; nt++) { o[nt][0]=o[nt][1]=o[nt][2]=o[nt][3]=0.f; }
    float m_lo = -1e30f, m_hi = -1e30f, l_lo = 0.f, l_hi = 0.f;

    const float* Kg = proj + (size_t)b*TT*NPROJ + C_K + h*64;
    const float* Vg = v    + (size_t)b*TT*HD   + h*64;

#define LOAD_TILE(buf, j0)                                                      \
    {                                                                           \
        _Pragma("unroll")                                                       \
        for (int it = 0; it < 4; it++) {                                        \
            int f = tid + it * 256;                                             \
            int krow = f >> 4, kseg = f & 15;                                   \
            cp_async16(sKu + ((buf)*64*KSTRIDE + krow*KSTRIDE + kseg*4)*4,      \
                       Kg + (size_t)((j0)+krow)*NPROJ + kseg*4);                \
            cp_async16(sVu + ((buf)*64*VSTRIDE + krow*VSTRIDE + kseg*4)*4,      \
                       Vg + (size_t)((j0)+krow)*HD + kseg*4);                   \
        }                                                                       \
    }

    LOAD_TILE(0, 0);
    cp_commit();

    for (int kt = 0; kt < TT/64; kt++) {
        if (kt + 1 < TT/64) { LOAD_TILE((kt+1)&1, (kt+1)*64); cp_commit(); cp_wait1(); }
        else cp_wait0();
        __syncthreads();

        const float* cK = sK + (kt & 1) * 64 * KSTRIDE;
        const float* cV = sV + (kt & 1) * 64 * VSTRIDE;

        float sc[8][4];
#pragma unroll
        for (int nt = 0; nt < 8; nt++) { sc[nt][0]=sc[nt][1]=sc[nt][2]=sc[nt][3]=0.f; }
#pragma unroll
        for (int kc = 0; kc < 8; kc++) {
#pragma unroll
            for (int nt = 0; nt < 8; nt++) {
                uint32_t bf[2];
                bf[0] = __float_as_uint(cK[(nt*8+lq)*KSTRIDE + kc*8 + lr]);
                bf[1] = __float_as_uint(cK[(nt*8+lq)*KSTRIDE + kc*8 + lr + 4]);
                mma_tf32(sc[nt], qa[kc], bf);
            }
        }

        float mxl = m_lo, mxh = m_hi;
#pragma unroll
        for (int nt = 0; nt < 8; nt++) {
            mxl = fmaxf(mxl, fmaxf(sc[nt][0], sc[nt][1]));
            mxh = fmaxf(mxh, fmaxf(sc[nt][2], sc[nt][3]));
        }
        mxl = fmaxf(mxl, __shfl_xor_sync(0xffffffffu, mxl, 1));
        mxl = fmaxf(mxl, __shfl_xor_sync(0xffffffffu, mxl, 2));
        mxh = fmaxf(mxh, __shfl_xor_sync(0xffffffffu, mxh, 1));
        mxh = fmaxf(mxh, __shfl_xor_sync(0xffffffffu, mxh, 2));
        float cl = ex2(m_lo - mxl), ch = ex2(m_hi - mxh);
        float sl = 0.f, sh = 0.f;
#pragma unroll
        for (int nt = 0; nt < 8; nt++) {
            sc[nt][0] = ex2(sc[nt][0] - mxl); sl += sc[nt][0];
            sc[nt][1] = ex2(sc[nt][1] - mxl); sl += sc[nt][1];
            sc[nt][2] = ex2(sc[nt][2] - mxh); sh += sc[nt][2];
            sc[nt][3] = ex2(sc[nt][3] - mxh); sh += sc[nt][3];
        }
        sl += __shfl_xor_sync(0xffffffffu, sl, 1);
        sl += __shfl_xor_sync(0xffffffffu, sl, 2);
        sh += __shfl_xor_sync(0xffffffffu, sh, 1);
        sh += __shfl_xor_sync(0xffffffffu, sh, 2);
        l_lo = l_lo * cl + sl;
        l_hi = l_hi * ch + sh;
        m_lo = mxl; m_hi = mxh;
#pragma unroll
        for (int nt = 0; nt < 8; nt++) {
            o[nt][0] *= cl; o[nt][1] *= cl;
            o[nt][2] *= ch; o[nt][3] *= ch;
        }

        const int srcA = (lane & ~3) | (lr >> 1);
        const bool odd = (lane & 1);
#pragma unroll
        for (int kc = 0; kc < 8; kc++) {
            float q0 = __shfl_sync(0xffffffffu, sc[kc][0], srcA);
            float q1 = __shfl_sync(0xffffffffu, sc[kc][1], srcA);
            float q2 = __shfl_sync(0xffffffffu, sc[kc][2], srcA);
            float q3 = __shfl_sync(0xffffffffu, sc[kc][3], srcA);
            float r0 = __shfl_sync(0xffffffffu, sc[kc][0], srcA + 2);
            float r1 = __shfl_sync(0xffffffffu, sc[kc][1], srcA + 2);
            float r2 = __shfl_sync(0xffffffffu, sc[kc][2], srcA + 2);
            float r3 = __shfl_sync(0xffffffffu, sc[kc][3], srcA + 2);
            uint32_t pa[4];
            pa[0] = f2tf32(odd ? q1 : q0);
            pa[1] = f2tf32(odd ? q3 : q2);
            pa[2] = f2tf32(odd ? r1 : r0);
            pa[3] = f2tf32(odd ? r3 : r2);
#pragma unroll
            for (int nt = 0; nt < 8; nt++) {
                uint32_t bf[2];
                bf[0] = __float_as_uint(cV[(kc*8+lr)*VSTRIDE + nt*8 + lq]);
                bf[1] = __float_as_uint(cV[(kc*8+lr+4)*VSTRIDE + nt*8 + lq]);
                mma_tf32(o[nt], pa, bf);
            }
        }
        __syncthreads();
    }
#undef LOAD_TILE

    float il = 1.f / l_lo, ih = 1.f / l_hi;
    float* oa = attn + (size_t)(b*TT + qbase + lq) * HD + h*64;
    float* ob = attn + (size_t)(b*TT + qbase + lq + 8) * HD + h*64;
#pragma unroll
    for (int nt = 0; nt < 8; nt++) {
        *(float2*)&oa[nt*8 + 2*lr] = make_float2(o[nt][0]*il, o[nt][1]*il);
        *(float2*)&ob[nt*8 + 2*lr] = make_float2(o[nt][2]*ih, o[nt][3]*ih);
    }
}

// ---------------- fused out-gate aggregation (warp per token) ----------------
__global__ __launch_bounds__(256) void out_gate_kernel(
    const float* __restrict__ glg, const float* __restrict__ attn, float* __restrict__ agg)
{
    const int bt   = blockIdx.x * 8 + (threadIdx.x >> 5);
    const int lane = threadIdx.x & 31;
    const float* arow = attn + (size_t)bt * HD;
    const float* g    = glg + (size_t)bt * NGATE + G_GLO;

    float acc[EE][2];
#pragma unroll
    for (int e = 0; e < EE; e++) { acc[e][0] = 0.f; acc[e][1] = 0.f; }

#pragma unroll
    for (int h = 0; h < HH; h++) {
        float2 a = *(const float2*)&arow[h * DHH + 2 * lane];
        float ga[5] = { g[h*5+0], g[h*5+1], g[h*5+2], g[h*5+3], g[h*5+4] };
        int i1, i2;
        top2_of5(ga, i1, i2);
#pragma unroll
        for (int e = 0; e < EE; e++) {
            if (e == i1 || e == i2) { acc[e][0] += a.x; acc[e][1] += a.y; }
        }
    }
    float* ar = agg + (size_t)bt * (EE * DHH);
#pragma unroll
    for (int e = 0; e < EE; e++) {
        float2 r;
        r.x = __uint_as_float(f2tf32(acc[e][0]));
        r.y = __uint_as_float(f2tf32(acc[e][1]));
        *(float2*)&ar[e * DHH + 2 * lane] = r;
    }
}

// ---------------- launcher ---------------------------------------------------
extern "C" void kernel_launch(void* const* d_in, const int* in_sizes, int n_in,
                              void* d_out, int out_size)
{
    const float* x  = (const float*)d_in[0];
    const float* Wq = (const float*)d_in[1];
    const float* Wk = (const float*)d_in[2];
    const float* Ws = (const float*)d_in[3];
    const float* Wd = (const float*)d_in[4];
    const float* Wv = (const float*)d_in[5];
    const float* Wo = (const float*)d_in[6];
    float* out = (float*)d_out;

    float *xt, *Bbig, *Bg, *WoT, *proj, *glgp, *glg, *v, *attn, *agg;
    cudaGetSymbolAddress((void**)&xt,   g_xt);
    cudaGetSymbolAddress((void**)&Bbig, g_Bbig);
    cudaGetSymbolAddress((void**)&Bg,   g_Bg);
    cudaGetSymbolAddress((void**)&WoT,  g_WoT);
    cudaGetSymbolAddress((void**)&proj, g_proj);
    cudaGetSymbolAddress((void**)&glgp, g_glgp);
    cudaGetSymbolAddress((void**)&glg,  g_glg);
    cudaGetSymbolAddress((void**)&v,    g_v);
    cudaGetSymbolAddress((void**)&attn, g_at);
    cudaGetSymbolAddress((void**)&agg,  g_agg);

    // No carveout attributes (R7 lesson). Only raise max dynamic smem.
    cudaFuncSetAttribute(tf32_gemm_kernel<0, true>,
                         cudaFuncAttributeMaxDynamicSharedMemorySize, GEMM_SMEM_BYTES);
    cudaFuncSetAttribute(tf32_gemm_kernel<0, false>,
                         cudaFuncAttributeMaxDynamicSharedMemorySize, GEMM_SMEM_BYTES);
    cudaFuncSetAttribute(tf32_gemm_kernel<3, false>,
                         cudaFuncAttributeMaxDynamicSharedMemorySize, GEMM_SMEM_BYTES);
    cudaFuncSetAttribute(flash_attn_tc_kernel,
                         cudaFuncAttributeMaxDynamicSharedMemorySize, FL_SMEM);

    // Fused pack pass (x->tf32, Bbig, Bg, Wo->tf32)
    {
        int n = PK_N4;
        pack_all_kernel<<<(n + 255) / 256, 256>>>(
            (const float4*)x, (uint4*)xt, Wq, Wk, Wv, (uint32_t*)Bbig,
            Ws, Wd, Bg, Wo, (uint32_t*)WoT);
    }

    // q/k/xv projection: raw-bit 1x (operands pre-rounded), outputs rounded
    tf32_gemm_kernel<0, true><<<dim3(NPROJ / 128, BT / 128), 256, GEMM_SMEM_BYTES>>>(
        xt, Bbig, proj, BT, NPROJ, DD, DD, NPROJ, NPROJ, 0, 0);

    // gate projection: 3xtf32 on ORIGINAL fp32 x, split-K x8, deterministic reduce
    tf32_gemm_kernel<3, false><<<dim3(1, BT / 128, GATE_NSPLIT), 256, GEMM_SMEM_BYTES>>>(
        x, Bg, glgp, BT, NGATE, GATE_KCHUNK, DD, NGATE, NGATE,
        GATE_KCHUNK, (size_t)BT * NGATE);
    {
        int n4 = BT * NGATE / 4;
        gate_reduce_kernel<<<(n4 + 255) / 256, 256>>>((const float4*)glgp, (float4*)glg);
    }

    // V combine (warp per token)
    v_combine_kernel<<<BT / 8, 256>>>(glg, proj, v);

    // Tensor-core flash attention (R8 config: KV tile 64, 1 CTA/SM)
    flash_attn_tc_kernel<<<dim3(TT / 128, BB * HH), 256, FL_SMEM>>>(proj, v, attn);

    // Output-gate aggregation (warp per token; writes tf32-rounded agg)
    out_gate_kernel<<<BT / 8, 256>>>(glg, attn, agg);

    // Output expert GEMM: raw-bit 1x  out = agg[8192,320] @ WoT[320,1024]
    tf32_gemm_kernel<0, false><<<dim3(DD / 128, BT / 128), 256, GEMM_SMEM_BYTES>>>(
        agg, WoT, out, BT, DD, EE * DHH, EE * DHH, DD, DD, 0, 0);
}

// round 11
// speedup vs baseline: 1.5106x; 1.5106x over previous
#include <cuda_runtime.h>
#include <cstdint>

#define BB   4
#define TT   2048
#define DD   1024
#define HH   8
#define DHH  64
#define EE   5
#define BT   (BB*TT)     // 8192
#define HD   (HH*DHH)    // 512
#define NPROJ 1408       // [q 512 | k 512 | xv 320 | pad 64]
#define NGATE 128        // [glv 40 | glo 40 | pad 48]
#define C_Q   0
#define C_K   512
#define C_XV  1024
#define G_GLV 0
#define G_GLO 40
#define GATE_NSPLIT 8
#define GATE_KCHUNK (DD/GATE_NSPLIT)   // 128

// ---------------- scratch (device globals; no allocations allowed) ----------
__device__ float g_xt  [BT*DD];                 // x pre-rounded to tf32
__device__ float g_Bbig[DD*NPROJ];              // packed [Wq|Wk|Wv|0] tf32
__device__ float g_Bg  [DD*NGATE];              // packed [Ws|Wd|0] fp32 (3x path)
__device__ float g_WoT [EE*DHH*DD];             // Wo pre-rounded to tf32
__device__ float g_proj[BT*NPROJ];
__device__ float g_glgp[GATE_NSPLIT*BT*NGATE];  // split-K partials
__device__ float g_glg [BT*NGATE];
__device__ float g_v   [BT*HD];
__device__ float g_at  [BT*HD];
__device__ float g_agg [BT*EE*DHH];             // tf32-rounded by out_gate

// ---------------- helpers ----------------------------------------------------
__device__ __forceinline__ uint32_t f2tf32(float x) {
    uint32_t r;
    asm("cvt.rna.tf32.f32 %0, %1;" : "=r"(r) : "f"(x));
    return r;
}
__device__ __forceinline__ void tf32_split(float x, uint32_t& hi, uint32_t& lo) {
    hi = f2tf32(x);
    lo = f2tf32(x - __uint_as_float(hi));
}
__device__ __forceinline__ float ex2(float x) {
    float r; asm("ex2.approx.ftz.f32 %0, %1;" : "=f"(r) : "f"(x)); return r;
}
__device__ __forceinline__ void cp_async16(uint32_t s, const void* g) {
    asm volatile("cp.async.cg.shared.global [%0], [%1], 16;" :: "r"(s), "l"(g));
}
__device__ __forceinline__ void cp_commit() { asm volatile("cp.async.commit_group;"); }
__device__ __forceinline__ void cp_wait0()  { asm volatile("cp.async.wait_group 0;"); }
__device__ __forceinline__ void cp_wait1()  { asm volatile("cp.async.wait_group 1;"); }
__device__ __forceinline__ void mma_tf32(float* c, const uint32_t* a, const uint32_t* b) {
    asm volatile(
        "mma.sync.aligned.m16n8k8.row.col.f32.tf32.tf32.f32 "
        "{%0,%1,%2,%3}, {%4,%5,%6,%7}, {%8,%9}, {%0,%1,%2,%3};"
        : "+f"(c[0]), "+f"(c[1]), "+f"(c[2]), "+f"(c[3])
        : "r"(a[0]), "r"(a[1]), "r"(a[2]), "r"(a[3]), "r"(b[0]), "r"(b[1]));
}

// ---------------- pack kernels ----------------------------------------------
__global__ void pack_x_kernel(const float4* __restrict__ x, uint4* __restrict__ y, int n4) {
    int i = blockIdx.x * 256 + threadIdx.x;
    if (i >= n4) return;
    float4 v = x[i];
    uint4 o;
    o.x = f2tf32(v.x); o.y = f2tf32(v.y); o.z = f2tf32(v.z); o.w = f2tf32(v.w);
    y[i] = o;
}
__global__ void pack_bbig_kernel(const float* __restrict__ Wq, const float* __restrict__ Wk,
                                 const float* __restrict__ Wv, uint32_t* __restrict__ Bb) {
    int idx = blockIdx.x * 256 + threadIdx.x;
    if (idx >= DD * NPROJ) return;
    int d = idx / NPROJ, c = idx % NPROJ;
    float v = 0.f;
    if      (c < 512)  v = Wq[d * 512 + c];
    else if (c < 1024) v = Wk[d * 512 + c - 512];
    else if (c < 1344) {
        int cc = c - 1024;
        int e = cc >> 6, kk = cc & 63;
        v = Wv[((size_t)e * DD + d) * 64 + kk];
    }
    Bb[idx] = f2tf32(v);
}
__global__ void pack_bg_kernel(const float* __restrict__ Ws, const float* __restrict__ Wd,
                               float* __restrict__ Bg) {
    int idx = blockIdx.x * 256 + threadIdx.x;
    if (idx >= DD * NGATE) return;
    int d = idx / NGATE, c = idx % NGATE;
    float v = 0.f;
    if      (c < 40) v = Ws[d * 40 + c];
    else if (c < 80) v = Wd[d * 40 + c - 40];
    Bg[idx] = v;
}
__global__ void pack_wo_kernel(const float* __restrict__ Wo, uint32_t* __restrict__ y, int n) {
    int i = blockIdx.x * 256 + threadIdx.x;
    if (i >= n) return;
    y[i] = f2tf32(Wo[i]);
}

// ---------------- tf32 tensor-core GEMM (SPLIT: 0=raw-bits, 1=cvt, 3=3x) ----
#define SA_STRIDE 36
#define SB_STRIDE 136
#define SA_FLOATS (128*SA_STRIDE)
#define SB_FLOATS (32*SB_STRIDE)
#define GEMM_SMEM_BYTES ((2*SA_FLOATS + 2*SB_FLOATS)*4)  // 71680

template<int SPLIT, bool ROUND>
__global__ __launch_bounds__(256) void tf32_gemm_kernel(
    const float* __restrict__ A, const float* __restrict__ B, float* __restrict__ C,
    int M, int N, int K, int lda, int ldb, int ldc, int ksplit, size_t csplit)
{
    extern __shared__ float smem[];
    float* sA = smem;
    float* sB = smem + 2 * SA_FLOATS;

    {
        const int z = blockIdx.z;
        const int kbeg = z * ksplit;
        A += kbeg;
        B += (size_t)kbeg * ldb;
        C += (size_t)z * csplit;
    }

    const int tid  = threadIdx.x;
    const int warp = tid >> 5, lane = tid & 31;
    const int lq = lane >> 2, lr = lane & 3;
    const int wm = (warp & 1) * 64;
    const int wn = (warp >> 1) * 32;
    const int bm = blockIdx.y * 128;
    const int bn = blockIdx.x * 128;

    float acc[4][4][4];
#pragma unroll
    for (int i = 0; i < 4; i++)
#pragma unroll
        for (int j = 0; j < 4; j++)
#pragma unroll
            for (int v = 0; v < 4; v++) acc[i][j][v] = 0.f;

    const uint32_t sA_base = (uint32_t)__cvta_generic_to_shared(sA);
    const uint32_t sB_base = (uint32_t)__cvta_generic_to_shared(sB);

#define COPY_STAGE(buf, k0)                                                     \
    {                                                                           \
        _Pragma("unroll")                                                       \
        for (int it = 0; it < 4; it++) {                                        \
            int f = tid + it * 256;                                             \
            int ar = f >> 3, ac4 = f & 7;                                       \
            cp_async16(sA_base + ((buf) * SA_FLOATS + ar * SA_STRIDE + ac4 * 4) * 4, \
                       A + (size_t)(bm + ar) * lda + (k0) + ac4 * 4);           \
            int br = f >> 5, bc4 = f & 31;                                      \
            cp_async16(sB_base + ((buf) * SB_FLOATS + br * SB_STRIDE + bc4 * 4) * 4, \
                       B + (size_t)((k0) + br) * ldb + bn + bc4 * 4);           \
        }                                                                       \
    }

    const int nk = K >> 5;
    COPY_STAGE(0, 0);
    cp_commit();

    for (int kt = 0; kt < nk; kt++) {
        if (kt + 1 < nk) {
            COPY_STAGE((kt + 1) & 1, (kt + 1) << 5);
            cp_commit();
            cp_wait1();
        } else {
            cp_wait0();
        }
        __syncthreads();

        const float* cA = sA + (kt & 1) * SA_FLOATS;
        const float* cB = sB + (kt & 1) * SB_FLOATS;
#pragma unroll
        for (int s = 0; s < 4; s++) {
            uint32_t ah[4][4], al[4][4], bh[4][2], bl[4][2];
#pragma unroll
            for (int i = 0; i < 4; i++) {
                int base = (wm + i * 16 + lq) * SA_STRIDE + s * 8 + lr;
                if (SPLIT == 3) {
                    tf32_split(cA[base],                  ah[i][0], al[i][0]);
                    tf32_split(cA[base + 8 * SA_STRIDE],  ah[i][1], al[i][1]);
                    tf32_split(cA[base + 4],              ah[i][2], al[i][2]);
                    tf32_split(cA[base + 8*SA_STRIDE+4],  ah[i][3], al[i][3]);
                } else if (SPLIT == 1) {
                    ah[i][0] = f2tf32(cA[base]);
                    ah[i][1] = f2tf32(cA[base + 8 * SA_STRIDE]);
                    ah[i][2] = f2tf32(cA[base + 4]);
                    ah[i][3] = f2tf32(cA[base + 8*SA_STRIDE+4]);
                } else {            // SPLIT == 0: operands pre-rounded to tf32
                    ah[i][0] = __float_as_uint(cA[base]);
                    ah[i][1] = __float_as_uint(cA[base + 8 * SA_STRIDE]);
                    ah[i][2] = __float_as_uint(cA[base + 4]);
                    ah[i][3] = __float_as_uint(cA[base + 8*SA_STRIDE+4]);
                }
            }
#pragma unroll
            for (int j = 0; j < 4; j++) {
                int base = (s * 8 + lr) * SB_STRIDE + wn + j * 8 + lq;
                if (SPLIT == 3) {
                    tf32_split(cB[base],                  bh[j][0], bl[j][0]);
                    tf32_split(cB[base + 4 * SB_STRIDE],  bh[j][1], bl[j][1]);
                } else if (SPLIT == 1) {
                    bh[j][0] = f2tf32(cB[base]);
                    bh[j][1] = f2tf32(cB[base + 4 * SB_STRIDE]);
                } else {
                    bh[j][0] = __float_as_uint(cB[base]);
                    bh[j][1] = __float_as_uint(cB[base + 4 * SB_STRIDE]);
                }
            }
#pragma unroll
            for (int i = 0; i < 4; i++)
#pragma unroll
                for (int j = 0; j < 4; j++) {
                    if (SPLIT == 3) {
                        mma_tf32(acc[i][j], ah[i], bl[j]);
                        mma_tf32(acc[i][j], al[i], bh[j]);
                    }
                    mma_tf32(acc[i][j], ah[i], bh[j]);
                }
        }
        __syncthreads();
    }
#undef COPY_STAGE

#pragma unroll
    for (int i = 0; i < 4; i++) {
        int r0 = bm + wm + i * 16 + lq;
#pragma unroll
        for (int j = 0; j < 4; j++) {
            int c0 = bn + wn + j * 8 + 2 * lr;
            float v0, v1, v2, v3;
            if (ROUND) {
                v0 = __uint_as_float(f2tf32(acc[i][j][0]));
                v1 = __uint_as_float(f2tf32(acc[i][j][1]));
                v2 = __uint_as_float(f2tf32(acc[i][j][2]));
                v3 = __uint_as_float(f2tf32(acc[i][j][3]));
            } else {
                v0 = acc[i][j][0]; v1 = acc[i][j][1];
                v2 = acc[i][j][2]; v3 = acc[i][j][3];
            }
            *(float2*)&C[(size_t)r0 * ldc + c0]       = make_float2(v0, v1);
            *(float2*)&C[(size_t)(r0 + 8) * ldc + c0] = make_float2(v2, v3);
        }
    }
}

// ---------------- split-K reduce (fixed order -> deterministic) --------------
__global__ void gate_reduce_kernel(const float4* __restrict__ part, float4* __restrict__ out) {
    int i = blockIdx.x * 256 + threadIdx.x;
    if (i >= BT * NGATE / 4) return;
    const int stride = BT * NGATE / 4;
    float4 r = part[i];
#pragma unroll
    for (int p = 1; p < GATE_NSPLIT; p++) {
        float4 a = part[i + p * stride];
        r.x += a.x; r.y += a.y; r.z += a.z; r.w += a.w;
    }
    out[i] = r;
}

// ---------------- top-2 helper ----------------------------------------------
__device__ __forceinline__ void top2_of5(const float g[5], int& i1, int& i2) {
    i1 = 0;
#pragma unroll
    for (int e = 1; e < 5; e++) if (g[e] > g[i1]) i1 = e;
    i2 = (i1 == 0) ? 1 : 0;
#pragma unroll
    for (int e = 0; e < 5; e++) if (e != i1 && g[e] > g[i2]) i2 = e;
}

// ---------------- fused V combine (warp per token) ---------------------------
__global__ __launch_bounds__(256) void v_combine_kernel(
    const float* __restrict__ glg, const float* __restrict__ proj, float* __restrict__ v)
{
    const int bt   = blockIdx.x * 8 + (threadIdx.x >> 5);
    const int lane = threadIdx.x & 31;
    const float* g  = glg + (size_t)bt * NGATE + G_GLV;
    const float* xv = proj + (size_t)bt * NPROJ + C_XV;
    float* vr = v + (size_t)bt * HD;
#pragma unroll
    for (int h = 0; h < HH; h++) {
        float ga[5] = { g[h*5+0], g[h*5+1], g[h*5+2], g[h*5+3], g[h*5+4] };
        int i1, i2;
        top2_of5(ga, i1, i2);
        float w1 = 1.f / (1.f + __expf(-ga[i1]));
        float w2 = 1.f / (1.f + __expf(-ga[i2]));
        float2 x1 = *(const float2*)&xv[i1 * DHH + 2 * lane];
        float2 x2 = *(const float2*)&xv[i2 * DHH + 2 * lane];
        float2 r;
        r.x = __uint_as_float(f2tf32(w1 * x1.x + w2 * x2.x));
        r.y = __uint_as_float(f2tf32(w1 * x1.y + w2 * x2.y));
        *(float2*)&vr[h * DHH + 2 * lane] = r;
    }
}

// ---------------- tensor-core flash attention --------------------------------
#define KSTRIDE 68
#define VSTRIDE 72
#define FL_SMEM ((2*64*KSTRIDE + 2*64*VSTRIDE)*4)   // 71680

__global__ __launch_bounds__(256) void flash_attn_tc_kernel(
    const float* __restrict__ proj, const float* __restrict__ v, float* __restrict__ attn)
{
    extern __shared__ float fsm[];
    float* sK = fsm;
    float* sV = fsm + 2*64*KSTRIDE;
    const int tid  = threadIdx.x;
    const int warp = tid >> 5, lane = tid & 31;
    const int lq = lane >> 2, lr = lane & 3;
    const int h = blockIdx.y & 7, b = blockIdx.y >> 3;
    const int qbase = blockIdx.x * 128 + warp * 16;

    const uint32_t sKu = (uint32_t)__cvta_generic_to_shared(sK);
    const uint32_t sVu = (uint32_t)__cvta_generic_to_shared(sV);

    const float QS = 0.1803368801f;   // 0.125 * log2(e)
    uint32_t qa[8][4];
    {
        const float* pa = proj + (size_t)(b*TT + qbase + lq) * NPROJ + C_Q + h*64;
        const float* pb = pa + (size_t)8 * NPROJ;
#pragma unroll
        for (int kc = 0; kc < 8; kc++) {
            qa[kc][0] = f2tf32(QS * pa[kc*8 + lr]);
            qa[kc][1] = f2tf32(QS * pb[kc*8 + lr]);
            qa[kc][2] = f2tf32(QS * pa[kc*8 + lr + 4]);
            qa[kc][3] = f2tf32(QS * pb[kc*8 + lr + 4]);
        }
    }

    float o[8][4];
#pragma unroll
    for (int nt = 0; nt < 8; nt++) { o[nt][0]=o[nt][1]=o[nt][2]=o[nt][3]=0.f; }
    float m_lo = -1e30f, m_hi = -1e30f, l_lo = 0.f, l_hi = 0.f;

    const float* Kg = proj + (size_t)b*TT*NPROJ + C_K + h*64;
    const float* Vg = v    + (size_t)b*TT*HD   + h*64;

#define LOAD_TILE(buf, j0)                                                      \
    {                                                                           \
        _Pragma("unroll")                                                       \
        for (int it = 0; it < 4; it++) {                                        \
            int f = tid + it * 256;                                             \
            int krow = f >> 4, kseg = f & 15;                                   \
            cp_async16(sKu + ((buf)*64*KSTRIDE + krow*KSTRIDE + kseg*4)*4,      \
                       Kg + (size_t)((j0)+krow)*NPROJ + kseg*4);                \
            cp_async16(sVu + ((buf)*64*VSTRIDE + krow*VSTRIDE + kseg*4)*4,      \
                       Vg + (size_t)((j0)+krow)*HD + kseg*4);                   \
        }                                                                       \
    }

    LOAD_TILE(0, 0);
    cp_commit();

    for (int kt = 0; kt < TT/64; kt++) {
        if (kt + 1 < TT/64) { LOAD_TILE((kt+1)&1, (kt+1)*64); cp_commit(); cp_wait1(); }
        else cp_wait0();
        __syncthreads();

        const float* cK = sK + (kt & 1) * 64 * KSTRIDE;
        const float* cV = sV + (kt & 1) * 64 * VSTRIDE;

        float sc[8][4];
#pragma unroll
        for (int nt = 0; nt < 8; nt++) { sc[nt][0]=sc[nt][1]=sc[nt][2]=sc[nt][3]=0.f; }
#pragma unroll
        for (int kc = 0; kc < 8; kc++) {
#pragma unroll
            for (int nt = 0; nt < 8; nt++) {
                uint32_t bf[2];
                bf[0] = __float_as_uint(cK[(nt*8+lq)*KSTRIDE + kc*8 + lr]);
                bf[1] = __float_as_uint(cK[(nt*8+lq)*KSTRIDE + kc*8 + lr + 4]);
                mma_tf32(sc[nt], qa[kc], bf);
            }
        }

        float mxl = m_lo, mxh = m_hi;
#pragma unroll
        for (int nt = 0; nt < 8; nt++) {
            mxl = fmaxf(mxl, fmaxf(sc[nt][0], sc[nt][1]));
            mxh = fmaxf(mxh, fmaxf(sc[nt][2], sc[nt][3]));
        }
        mxl = fmaxf(mxl, __shfl_xor_sync(0xffffffffu, mxl, 1));
        mxl = fmaxf(mxl, __shfl_xor_sync(0xffffffffu, mxl, 2));
        mxh = fmaxf(mxh, __shfl_xor_sync(0xffffffffu, mxh, 1));
        mxh = fmaxf(mxh, __shfl_xor_sync(0xffffffffu, mxh, 2));
        float cl = ex2(m_lo - mxl), ch = ex2(m_hi - mxh);
        float sl = 0.f, sh = 0.f;
#pragma unroll
        for (int nt = 0; nt < 8; nt++) {
            sc[nt][0] = ex2(sc[nt][0] - mxl); sl += sc[nt][0];
            sc[nt][1] = ex2(sc[nt][1] - mxl); sl += sc[nt][1];
            sc[nt][2] = ex2(sc[nt][2] - mxh); sh += sc[nt][2];
            sc[nt][3] = ex2(sc[nt][3] - mxh); sh += sc[nt][3];
        }
        sl += __shfl_xor_sync(0xffffffffu, sl, 1);
        sl += __shfl_xor_sync(0xffffffffu, sl, 2);
        sh += __shfl_xor_sync(0xffffffffu, sh, 1);
        sh += __shfl_xor_sync(0xffffffffu, sh, 2);
        l_lo = l_lo * cl + sl;
        l_hi = l_hi * ch + sh;
        m_lo = mxl; m_hi = mxh;
#pragma unroll
        for (int nt = 0; nt < 8; nt++) {
            o[nt][0] *= cl; o[nt][1] *= cl;
            o[nt][2] *= ch; o[nt][3] *= ch;
        }

        const int srcA = (lane & ~3) | (lr >> 1);
        const bool odd = (lane & 1);
#pragma unroll
        for (int kc = 0; kc < 8; kc++) {
            float q0 = __shfl_sync(0xffffffffu, sc[kc][0], srcA);
            float q1 = __shfl_sync(0xffffffffu, sc[kc][1], srcA);
            float q2 = __shfl_sync(0xffffffffu, sc[kc][2], srcA);
            float q3 = __shfl_sync(0xffffffffu, sc[kc][3], srcA);
            float r0 = __shfl_sync(0xffffffffu, sc[kc][0], srcA + 2);
            float r1 = __shfl_sync(0xffffffffu, sc[kc][1], srcA + 2);
            float r2 = __shfl_sync(0xffffffffu, sc[kc][2], srcA + 2);
            float r3 = __shfl_sync(0xffffffffu, sc[kc][3], srcA + 2);
            uint32_t pa[4];
            pa[0] = f2tf32(odd ? q1 : q0);
            pa[1] = f2tf32(odd ? q3 : q2);
            pa[2] = f2tf32(odd ? r1 : r0);
            pa[3] = f2tf32(odd ? r3 : r2);
#pragma unroll
            for (int nt = 0; nt < 8; nt++) {
                uint32_t bf[2];
                bf[0] = __float_as_uint(cV[(kc*8+lr)*VSTRIDE + nt*8 + lq]);
                bf[1] = __float_as_uint(cV[(kc*8+lr+4)*VSTRIDE + nt*8 + lq]);
                mma_tf32(o[nt], pa, bf);
            }
        }
        __syncthreads();
    }
#undef LOAD_TILE

    float il = 1.f / l_lo, ih = 1.f / l_hi;
    float* oa = attn + (size_t)(b*TT + qbase + lq) * HD + h*64;
    float* ob = attn + (size_t)(b*TT + qbase + lq + 8) * HD + h*64;
#pragma unroll
    for (int nt = 0; nt < 8; nt++) {
        *(float2*)&oa[nt*8 + 2*lr] = make_float2(o[nt][0]*il, o[nt][1]*il);
        *(float2*)&ob[nt*8 + 2*lr] = make_float2(o[nt][2]*ih, o[nt][3]*ih);
    }
}

// ---------------- fused out-gate aggregation (warp per token) ----------------
// Writes agg pre-rounded to tf32 so the out GEMM can run the raw-bit path.
__global__ __launch_bounds__(256) void out_gate_kernel(
    const float* __restrict__ glg, const float* __restrict__ attn, float* __restrict__ agg)
{
    const int bt   = blockIdx.x * 8 + (threadIdx.x >> 5);
    const int lane = threadIdx.x & 31;
    const float* arow = attn + (size_t)bt * HD;
    const float* g    = glg + (size_t)bt * NGATE + G_GLO;

    float acc[EE][2];
#pragma unroll
    for (int e = 0; e < EE; e++) { acc[e][0] = 0.f; acc[e][1] = 0.f; }

#pragma unroll
    for (int h = 0; h < HH; h++) {
        float2 a = *(const float2*)&arow[h * DHH + 2 * lane];
        float ga[5] = { g[h*5+0], g[h*5+1], g[h*5+2], g[h*5+3], g[h*5+4] };
        int i1, i2;
        top2_of5(ga, i1, i2);
#pragma unroll
        for (int e = 0; e < EE; e++) {
            if (e == i1 || e == i2) { acc[e][0] += a.x; acc[e][1] += a.y; }
        }
    }
    float* ar = agg + (size_t)bt * (EE * DHH);
#pragma unroll
    for (int e = 0; e < EE; e++) {
        float2 r;
        r.x = __uint_as_float(f2tf32(acc[e][0]));
        r.y = __uint_as_float(f2tf32(acc[e][1]));
        *(float2*)&ar[e * DHH + 2 * lane] = r;
    }
}

// ---------------- launcher ---------------------------------------------------
extern "C" void kernel_launch(void* const* d_in, const int* in_sizes, int n_in,
                              void* d_out, int out_size)
{
    const float* x  = (const float*)d_in[0];
    const float* Wq = (const float*)d_in[1];
    const float* Wk = (const float*)d_in[2];
    const float* Ws = (const float*)d_in[3];
    const float* Wd = (const float*)d_in[4];
    const float* Wv = (const float*)d_in[5];
    const float* Wo = (const float*)d_in[6];
    float* out = (float*)d_out;

    float *xt, *Bbig, *Bg, *WoT, *proj, *glgp, *glg, *v, *attn, *agg;
    cudaGetSymbolAddress((void**)&xt,   g_xt);
    cudaGetSymbolAddress((void**)&Bbig, g_Bbig);
    cudaGetSymbolAddress((void**)&Bg,   g_Bg);
    cudaGetSymbolAddress((void**)&WoT,  g_WoT);
    cudaGetSymbolAddress((void**)&proj, g_proj);
    cudaGetSymbolAddress((void**)&glgp, g_glgp);
    cudaGetSymbolAddress((void**)&glg,  g_glg);
    cudaGetSymbolAddress((void**)&v,    g_v);
    cudaGetSymbolAddress((void**)&attn, g_at);
    cudaGetSymbolAddress((void**)&agg,  g_agg);

    // No carveout attributes (R7 lesson). Only raise max dynamic smem.
    cudaFuncSetAttribute(tf32_gemm_kernel<0, true>,
                         cudaFuncAttributeMaxDynamicSharedMemorySize, GEMM_SMEM_BYTES);
    cudaFuncSetAttribute(tf32_gemm_kernel<0, false>,
                         cudaFuncAttributeMaxDynamicSharedMemorySize, GEMM_SMEM_BYTES);
    cudaFuncSetAttribute(tf32_gemm_kernel<3, false>,
                         cudaFuncAttributeMaxDynamicSharedMemorySize, GEMM_SMEM_BYTES);
    cudaFuncSetAttribute(flash_attn_tc_kernel,
                         cudaFuncAttributeMaxDynamicSharedMemorySize, FL_SMEM);

    // Pack inputs (pre-round everything the raw-bit GEMMs consume)
    {
        int n4 = BT * DD / 4;
        pack_x_kernel<<<(n4 + 255) / 256, 256>>>((const float4*)x, (uint4*)xt, n4);
        int nb = DD * NPROJ;
        pack_bbig_kernel<<<(nb + 255) / 256, 256>>>(Wq, Wk, Wv, (uint32_t*)Bbig);
        int ng = DD * NGATE;
        pack_bg_kernel<<<(ng + 255) / 256, 256>>>(Ws, Wd, Bg);
        int nw = EE * DHH * DD;
        pack_wo_kernel<<<(nw + 255) / 256, 256>>>(Wo, (uint32_t*)WoT, nw);
    }

    // q/k/xv projection: raw-bit 1x (operands pre-rounded), outputs rounded
    tf32_gemm_kernel<0, true><<<dim3(NPROJ / 128, BT / 128), 256, GEMM_SMEM_BYTES>>>(
        xt, Bbig, proj, BT, NPROJ, DD, DD, NPROJ, NPROJ, 0, 0);

    // gate projection: 3xtf32 on ORIGINAL fp32 x, split-K x8, deterministic reduce
    tf32_gemm_kernel<3, false><<<dim3(1, BT / 128, GATE_NSPLIT), 256, GEMM_SMEM_BYTES>>>(
        x, Bg, glgp, BT, NGATE, GATE_KCHUNK, DD, NGATE, NGATE,
        GATE_KCHUNK, (size_t)BT * NGATE);
    {
        int n4 = BT * NGATE / 4;
        gate_reduce_kernel<<<(n4 + 255) / 256, 256>>>((const float4*)glgp, (float4*)glg);
    }

    // V combine (warp per token)
    v_combine_kernel<<<BT / 8, 256>>>(glg, proj, v);

    // Tensor-core flash attention
    flash_attn_tc_kernel<<<dim3(TT / 128, BB * HH), 256, FL_SMEM>>>(proj, v, attn);

    // Output-gate aggregation (warp per token; writes tf32-rounded agg)
    out_gate_kernel<<<BT / 8, 256>>>(glg, attn, agg);

    // Output expert GEMM: raw-bit 1x  out = agg[8192,320] @ WoT[320,1024]
    tf32_gemm_kernel<0, false><<<dim3(DD / 128, BT / 128), 256, GEMM_SMEM_BYTES>>>(
        agg, WoT, out, BT, DD, EE * DHH, EE * DHH, DD, DD, 0, 0);
}

// round 13
// speedup vs baseline: 1.5612x; 1.0335x over previous
#include <cuda_runtime.h>
#include <cstdint>

#define BB   4
#define TT   2048
#define DD   1024
#define HH   8
#define DHH  64
#define EE   5
#define BT   (BB*TT)     // 8192
#define HD   (HH*DHH)    // 512
#define NPROJ 1408       // [q 512 | k 512 | xv 320 | pad 64]
#define NGATE 128        // [glv 40 | glo 40 | pad 48]
#define C_Q   0
#define C_K   512
#define C_XV  1024
#define G_GLV 0
#define G_GLO 40
#define GATE_NSPLIT 8
#define GATE_KCHUNK (DD/GATE_NSPLIT)   // 128

// ---------------- scratch (device globals; no allocations allowed) ----------
__device__ float g_xt  [BT*DD];                 // x pre-rounded to tf32
__device__ float g_Bbig[DD*NPROJ];              // packed [Wq|Wk|Wv|0] tf32
__device__ float g_Bg  [DD*NGATE];              // packed [Ws|Wd|0] fp32 (3x path)
__device__ float g_WoT [EE*DHH*DD];             // Wo pre-rounded to tf32
__device__ float g_proj[BT*NPROJ];
__device__ float g_glgp[GATE_NSPLIT*BT*NGATE];  // split-K partials
__device__ float g_glg [BT*NGATE];
__device__ float g_v   [BT*HD];
__device__ float g_at  [BT*HD];
__device__ float g_agg [BT*EE*DHH];             // tf32-rounded by out_gate

// ---------------- helpers ----------------------------------------------------
__device__ __forceinline__ uint32_t f2tf32(float x) {
    uint32_t r;
    asm("cvt.rna.tf32.f32 %0, %1;" : "=r"(r) : "f"(x));
    return r;
}
__device__ __forceinline__ void tf32_split(float x, uint32_t& hi, uint32_t& lo) {
    hi = f2tf32(x);
    lo = f2tf32(x - __uint_as_float(hi));
}
__device__ __forceinline__ float ex2(float x) {
    float r; asm("ex2.approx.ftz.f32 %0, %1;" : "=f"(r) : "f"(x)); return r;
}
__device__ __forceinline__ void cp_async16(uint32_t s, const void* g) {
    asm volatile("cp.async.cg.shared.global [%0], [%1], 16;" :: "r"(s), "l"(g));
}
__device__ __forceinline__ void cp_commit() { asm volatile("cp.async.commit_group;"); }
__device__ __forceinline__ void cp_wait0()  { asm volatile("cp.async.wait_group 0;"); }
__device__ __forceinline__ void cp_wait1()  { asm volatile("cp.async.wait_group 1;"); }
__device__ __forceinline__ void mma_tf32(float* c, const uint32_t* a, const uint32_t* b) {
    asm volatile(
        "mma.sync.aligned.m16n8k8.row.col.f32.tf32.tf32.f32 "
        "{%0,%1,%2,%3}, {%4,%5,%6,%7}, {%8,%9}, {%0,%1,%2,%3};"
        : "+f"(c[0]), "+f"(c[1]), "+f"(c[2]), "+f"(c[3])
        : "r"(a[0]), "r"(a[1]), "r"(a[2]), "r"(a[3]), "r"(b[0]), "r"(b[1]));
}

// ---------------- pack kernels ----------------------------------------------
__global__ void pack_x_kernel(const float4* __restrict__ x, uint4* __restrict__ y, int n4) {
    int i = blockIdx.x * 256 + threadIdx.x;
    if (i >= n4) return;
    float4 v = x[i];
    uint4 o;
    o.x = f2tf32(v.x); o.y = f2tf32(v.y); o.z = f2tf32(v.z); o.w = f2tf32(v.w);
    y[i] = o;
}
__global__ void pack_bbig_kernel(const float* __restrict__ Wq, const float* __restrict__ Wk,
                                 const float* __restrict__ Wv, uint32_t* __restrict__ Bb) {
    int idx = blockIdx.x * 256 + threadIdx.x;
    if (idx >= DD * NPROJ) return;
    int d = idx / NPROJ, c = idx % NPROJ;
    float v = 0.f;
    if      (c < 512)  v = Wq[d * 512 + c];
    else if (c < 1024) v = Wk[d * 512 + c - 512];
    else if (c < 1344) {
        int cc = c - 1024;
        int e = cc >> 6, kk = cc & 63;
        v = Wv[((size_t)e * DD + d) * 64 + kk];
    }
    Bb[idx] = f2tf32(v);
}
__global__ void pack_bg_kernel(const float* __restrict__ Ws, const float* __restrict__ Wd,
                               float* __restrict__ Bg) {
    int idx = blockIdx.x * 256 + threadIdx.x;
    if (idx >= DD * NGATE) return;
    int d = idx / NGATE, c = idx % NGATE;
    float v = 0.f;
    if      (c < 40) v = Ws[d * 40 + c];
    else if (c < 80) v = Wd[d * 40 + c - 40];
    Bg[idx] = v;
}
__global__ void pack_wo_kernel(const float* __restrict__ Wo, uint32_t* __restrict__ y, int n) {
    int i = blockIdx.x * 256 + threadIdx.x;
    if (i >= n) return;
    y[i] = f2tf32(Wo[i]);
}

// ---------------- tf32 tensor-core GEMM (SPLIT: 0=raw-bits, 1=cvt, 3=3x) ----
#define SA_STRIDE 36
#define SB_STRIDE 136
#define SA_FLOATS (128*SA_STRIDE)
#define SB_FLOATS (32*SB_STRIDE)
#define GEMM_SMEM_BYTES ((2*SA_FLOATS + 2*SB_FLOATS)*4)  // 71680

template<int SPLIT, bool ROUND>
__global__ __launch_bounds__(256) void tf32_gemm_kernel(
    const float* __restrict__ A, const float* __restrict__ B, float* __restrict__ C,
    int M, int N, int K, int lda, int ldb, int ldc, int ksplit, size_t csplit)
{
    extern __shared__ float smem[];
    float* sA = smem;
    float* sB = smem + 2 * SA_FLOATS;

    {
        const int z = blockIdx.z;
        const int kbeg = z * ksplit;
        A += kbeg;
        B += (size_t)kbeg * ldb;
        C += (size_t)z * csplit;
    }

    const int tid  = threadIdx.x;
    const int warp = tid >> 5, lane = tid & 31;
    const int lq = lane >> 2, lr = lane & 3;
    const int wm = (warp & 1) * 64;
    const int wn = (warp >> 1) * 32;
    const int bm = blockIdx.y * 128;
    const int bn = blockIdx.x * 128;

    float acc[4][4][4];
#pragma unroll
    for (int i = 0; i < 4; i++)
#pragma unroll
        for (int j = 0; j < 4; j++)
#pragma unroll
            for (int v = 0; v < 4; v++) acc[i][j][v] = 0.f;

    const uint32_t sA_base = (uint32_t)__cvta_generic_to_shared(sA);
    const uint32_t sB_base = (uint32_t)__cvta_generic_to_shared(sB);

#define COPY_STAGE(buf, k0)                                                     \
    {                                                                           \
        _Pragma("unroll")                                                       \
        for (int it = 0; it < 4; it++) {                                        \
            int f = tid + it * 256;                                             \
            int ar = f >> 3, ac4 = f & 7;                                       \
            cp_async16(sA_base + ((buf) * SA_FLOATS + ar * SA_STRIDE + ac4 * 4) * 4, \
                       A + (size_t)(bm + ar) * lda + (k0) + ac4 * 4);           \
            int br = f >> 5, bc4 = f & 31;                                      \
            cp_async16(sB_base + ((buf) * SB_FLOATS + br * SB_STRIDE + bc4 * 4) * 4, \
                       B + (size_t)((k0) + br) * ldb + bn + bc4 * 4);           \
        }                                                                       \
    }

    const int nk = K >> 5;
    COPY_STAGE(0, 0);
    cp_commit();

    for (int kt = 0; kt < nk; kt++) {
        if (kt + 1 < nk) {
            COPY_STAGE((kt + 1) & 1, (kt + 1) << 5);
            cp_commit();
            cp_wait1();
        } else {
            cp_wait0();
        }
        __syncthreads();

        const float* cA = sA + (kt & 1) * SA_FLOATS;
        const float* cB = sB + (kt & 1) * SB_FLOATS;
#pragma unroll
        for (int s = 0; s < 4; s++) {
            uint32_t ah[4][4], al[4][4], bh[4][2], bl[4][2];
#pragma unroll
            for (int i = 0; i < 4; i++) {
                int base = (wm + i * 16 + lq) * SA_STRIDE + s * 8 + lr;
                if (SPLIT == 3) {
                    tf32_split(cA[base],                  ah[i][0], al[i][0]);
                    tf32_split(cA[base + 8 * SA_STRIDE],  ah[i][1], al[i][1]);
                    tf32_split(cA[base + 4],              ah[i][2], al[i][2]);
                    tf32_split(cA[base + 8*SA_STRIDE+4],  ah[i][3], al[i][3]);
                } else if (SPLIT == 1) {
                    ah[i][0] = f2tf32(cA[base]);
                    ah[i][1] = f2tf32(cA[base + 8 * SA_STRIDE]);
                    ah[i][2] = f2tf32(cA[base + 4]);
                    ah[i][3] = f2tf32(cA[base + 8*SA_STRIDE+4]);
                } else {            // SPLIT == 0: operands pre-rounded to tf32
                    ah[i][0] = __float_as_uint(cA[base]);
                    ah[i][1] = __float_as_uint(cA[base + 8 * SA_STRIDE]);
                    ah[i][2] = __float_as_uint(cA[base + 4]);
                    ah[i][3] = __float_as_uint(cA[base + 8*SA_STRIDE+4]);
                }
            }
#pragma unroll
            for (int j = 0; j < 4; j++) {
                int base = (s * 8 + lr) * SB_STRIDE + wn + j * 8 + lq;
                if (SPLIT == 3) {
                    tf32_split(cB[base],                  bh[j][0], bl[j][0]);
                    tf32_split(cB[base + 4 * SB_STRIDE],  bh[j][1], bl[j][1]);
                } else if (SPLIT == 1) {
                    bh[j][0] = f2tf32(cB[base]);
                    bh[j][1] = f2tf32(cB[base + 4 * SB_STRIDE]);
                } else {
                    bh[j][0] = __float_as_uint(cB[base]);
                    bh[j][1] = __float_as_uint(cB[base + 4 * SB_STRIDE]);
                }
            }
#pragma unroll
            for (int i = 0; i < 4; i++)
#pragma unroll
                for (int j = 0; j < 4; j++) {
                    if (SPLIT == 3) {
                        mma_tf32(acc[i][j], ah[i], bl[j]);
                        mma_tf32(acc[i][j], al[i], bh[j]);
                    }
                    mma_tf32(acc[i][j], ah[i], bh[j]);
                }
        }
        __syncthreads();
    }
#undef COPY_STAGE

#pragma unroll
    for (int i = 0; i < 4; i++) {
        int r0 = bm + wm + i * 16 + lq;
#pragma unroll
        for (int j = 0; j < 4; j++) {
            int c0 = bn + wn + j * 8 + 2 * lr;
            float v0, v1, v2, v3;
            if (ROUND) {
                v0 = __uint_as_float(f2tf32(acc[i][j][0]));
                v1 = __uint_as_float(f2tf32(acc[i][j][1]));
                v2 = __uint_as_float(f2tf32(acc[i][j][2]));
                v3 = __uint_as_float(f2tf32(acc[i][j][3]));
            } else {
                v0 = acc[i][j][0]; v1 = acc[i][j][1];
                v2 = acc[i][j][2]; v3 = acc[i][j][3];
            }
            *(float2*)&C[(size_t)r0 * ldc + c0]       = make_float2(v0, v1);
            *(float2*)&C[(size_t)(r0 + 8) * ldc + c0] = make_float2(v2, v3);
        }
    }
}

// ---------------- split-K reduce (fixed order -> deterministic) --------------
__global__ void gate_reduce_kernel(const float4* __restrict__ part, float4* __restrict__ out) {
    int i = blockIdx.x * 256 + threadIdx.x;
    if (i >= BT * NGATE / 4) return;
    const int stride = BT * NGATE / 4;
    float4 r = part[i];
#pragma unroll
    for (int p = 1; p < GATE_NSPLIT; p++) {
        float4 a = part[i + p * stride];
        r.x += a.x; r.y += a.y; r.z += a.z; r.w += a.w;
    }
    out[i] = r;
}

// ---------------- top-2 helper ----------------------------------------------
__device__ __forceinline__ void top2_of5(const float g[5], int& i1, int& i2) {
    i1 = 0;
#pragma unroll
    for (int e = 1; e < 5; e++) if (g[e] > g[i1]) i1 = e;
    i2 = (i1 == 0) ? 1 : 0;
#pragma unroll
    for (int e = 0; e < 5; e++) if (e != i1 && g[e] > g[i2]) i2 = e;
}

// ---------------- fused V combine (warp per token) ---------------------------
__global__ __launch_bounds__(256) void v_combine_kernel(
    const float* __restrict__ glg, const float* __restrict__ proj, float* __restrict__ v)
{
    const int bt   = blockIdx.x * 8 + (threadIdx.x >> 5);
    const int lane = threadIdx.x & 31;
    const float* g  = glg + (size_t)bt * NGATE + G_GLV;
    const float* xv = proj + (size_t)bt * NPROJ + C_XV;
    float* vr = v + (size_t)bt * HD;
#pragma unroll
    for (int h = 0; h < HH; h++) {
        float ga[5] = { g[h*5+0], g[h*5+1], g[h*5+2], g[h*5+3], g[h*5+4] };
        int i1, i2;
        top2_of5(ga, i1, i2);
        float w1 = 1.f / (1.f + __expf(-ga[i1]));
        float w2 = 1.f / (1.f + __expf(-ga[i2]));
        float2 x1 = *(const float2*)&xv[i1 * DHH + 2 * lane];
        float2 x2 = *(const float2*)&xv[i2 * DHH + 2 * lane];
        float2 r;
        r.x = __uint_as_float(f2tf32(w1 * x1.x + w2 * x2.x));
        r.y = __uint_as_float(f2tf32(w1 * x1.y + w2 * x2.y));
        *(float2*)&vr[h * DHH + 2 * lane] = r;
    }
}

// ---------------- tensor-core flash attention --------------------------------
#define KSTRIDE 68
#define VSTRIDE 72
#define FL_SMEM ((2*64*KSTRIDE + 2*64*VSTRIDE)*4)   // 71680

__global__ __launch_bounds__(256) void flash_attn_tc_kernel(
    const float* __restrict__ proj, const float* __restrict__ v, float* __restrict__ attn)
{
    extern __shared__ float fsm[];
    float* sK = fsm;
    float* sV = fsm + 2*64*KSTRIDE;
    const int tid  = threadIdx.x;
    const int warp = tid >> 5, lane = tid & 31;
    const int lq = lane >> 2, lr = lane & 3;
    const int h = blockIdx.y & 7, b = blockIdx.y >> 3;
    const int qbase = blockIdx.x * 128 + warp * 16;

    const uint32_t sKu = (uint32_t)__cvta_generic_to_shared(sK);
    const uint32_t sVu = (uint32_t)__cvta_generic_to_shared(sV);

    const float QS = 0.1803368801f;   // 0.125 * log2(e)
    uint32_t qa[8][4];
    {
        const float* pa = proj + (size_t)(b*TT + qbase + lq) * NPROJ + C_Q + h*64;
        const float* pb = pa + (size_t)8 * NPROJ;
#pragma unroll
        for (int kc = 0; kc < 8; kc++) {
            qa[kc][0] = f2tf32(QS * pa[kc*8 + lr]);
            qa[kc][1] = f2tf32(QS * pb[kc*8 + lr]);
            qa[kc][2] = f2tf32(QS * pa[kc*8 + lr + 4]);
            qa[kc][3] = f2tf32(QS * pb[kc*8 + lr + 4]);
        }
    }

    float o[8][4];
#pragma unroll
    for (int nt = 0; nt < 8; nt++) { o[nt][0]=o[nt][1]=o[nt][2]=o[nt][3]=0.f; }
    float m_lo = -1e30f, m_hi = -1e30f, l_lo = 0.f, l_hi = 0.f;

    const float* Kg = proj + (size_t)b*TT*NPROJ + C_K + h*64;
    const float* Vg = v    + (size_t)b*TT*HD   + h*64;

#define LOAD_TILE(buf, j0)                                                      \
    {                                                                           \
        _Pragma("unroll")                                                       \
        for (int it = 0; it < 4; it++) {                                        \
            int f = tid + it * 256;                                             \
            int krow = f >> 4, kseg = f & 15;                                   \
            cp_async16(sKu + ((buf)*64*KSTRIDE + krow*KSTRIDE + kseg*4)*4,      \
                       Kg + (size_t)((j0)+krow)*NPROJ + kseg*4);                \
            cp_async16(sVu + ((buf)*64*VSTRIDE + krow*VSTRIDE + kseg*4)*4,      \
                       Vg + (size_t)((j0)+krow)*HD + kseg*4);                   \
        }                                                                       \
    }

    LOAD_TILE(0, 0);
    cp_commit();

    for (int kt = 0; kt < TT/64; kt++) {
        if (kt + 1 < TT/64) { LOAD_TILE((kt+1)&1, (kt+1)*64); cp_commit(); cp_wait1(); }
        else cp_wait0();
        __syncthreads();

        const float* cK = sK + (kt & 1) * 64 * KSTRIDE;
        const float* cV = sV + (kt & 1) * 64 * VSTRIDE;

        float sc[8][4];
#pragma unroll
        for (int nt = 0; nt < 8; nt++) { sc[nt][0]=sc[nt][1]=sc[nt][2]=sc[nt][3]=0.f; }
#pragma unroll
        for (int kc = 0; kc < 8; kc++) {
#pragma unroll
            for (int nt = 0; nt < 8; nt++) {
                uint32_t bf[2];
                bf[0] = __float_as_uint(cK[(nt*8+lq)*KSTRIDE + kc*8 + lr]);
                bf[1] = __float_as_uint(cK[(nt*8+lq)*KSTRIDE + kc*8 + lr + 4]);
                mma_tf32(sc[nt], qa[kc], bf);
            }
        }

        float mxl = m_lo, mxh = m_hi;
#pragma unroll
        for (int nt = 0; nt < 8; nt++) {
            mxl = fmaxf(mxl, fmaxf(sc[nt][0], sc[nt][1]));
            mxh = fmaxf(mxh, fmaxf(sc[nt][2], sc[nt][3]));
        }
        mxl = fmaxf(mxl, __shfl_xor_sync(0xffffffffu, mxl, 1));
        mxl = fmaxf(mxl, __shfl_xor_sync(0xffffffffu, mxl, 2));
        mxh = fmaxf(mxh, __shfl_xor_sync(0xffffffffu, mxh, 1));
        mxh = fmaxf(mxh, __shfl_xor_sync(0xffffffffu, mxh, 2));
        float cl = ex2(m_lo - mxl), ch = ex2(m_hi - mxh);
        float sl = 0.f, sh = 0.f;
#pragma unroll
        for (int nt = 0; nt < 8; nt++) {
            sc[nt][0] = ex2(sc[nt][0] - mxl); sl += sc[nt][0];
            sc[nt][1] = ex2(sc[nt][1] - mxl); sl += sc[nt][1];
            sc[nt][2] = ex2(sc[nt][2] - mxh); sh += sc[nt][2];
            sc[nt][3] = ex2(sc[nt][3] - mxh); sh += sc[nt][3];
        }
        sl += __shfl_xor_sync(0xffffffffu, sl, 1);
        sl += __shfl_xor_sync(0xffffffffu, sl, 2);
        sh += __shfl_xor_sync(0xffffffffu, sh, 1);
        sh += __shfl_xor_sync(0xffffffffu, sh, 2);
        l_lo = l_lo * cl + sl;
        l_hi = l_hi * ch + sh;
        m_lo = mxl; m_hi = mxh;
#pragma unroll
        for (int nt = 0; nt < 8; nt++) {
            o[nt][0] *= cl; o[nt][1] *= cl;
            o[nt][2] *= ch; o[nt][3] *= ch;
        }

        const int srcA = (lane & ~3) | (lr >> 1);
        const bool odd = (lane & 1);
#pragma unroll
        for (int kc = 0; kc < 8; kc++) {
            float q0 = __shfl_sync(0xffffffffu, sc[kc][0], srcA);
            float q1 = __shfl_sync(0xffffffffu, sc[kc][1], srcA);
            float q2 = __shfl_sync(0xffffffffu, sc[kc][2], srcA);
            float q3 = __shfl_sync(0xffffffffu, sc[kc][3], srcA);
            float r0 = __shfl_sync(0xffffffffu, sc[kc][0], srcA + 2);
            float r1 = __shfl_sync(0xffffffffu, sc[kc][1], srcA + 2);
            float r2 = __shfl_sync(0xffffffffu, sc[kc][2], srcA + 2);
            float r3 = __shfl_sync(0xffffffffu, sc[kc][3], srcA + 2);
            uint32_t pa[4];
            pa[0] = f2tf32(odd ? q1 : q0);
            pa[1] = f2tf32(odd ? q3 : q2);
            pa[2] = f2tf32(odd ? r1 : r0);
            pa[3] = f2tf32(odd ? r3 : r2);
#pragma unroll
            for (int nt = 0; nt < 8; nt++) {
                uint32_t bf[2];
                bf[0] = __float_as_uint(cV[(kc*8+lr)*VSTRIDE + nt*8 + lq]);
                bf[1] = __float_as_uint(cV[(kc*8+lr+4)*VSTRIDE + nt*8 + lq]);
                mma_tf32(o[nt], pa, bf);
            }
        }
        __syncthreads();
    }
#undef LOAD_TILE

    float il = 1.f / l_lo, ih = 1.f / l_hi;
    float* oa = attn + (size_t)(b*TT + qbase + lq) * HD + h*64;
    float* ob = attn + (size_t)(b*TT + qbase + lq + 8) * HD + h*64;
#pragma unroll
    for (int nt = 0; nt < 8; nt++) {
        *(float2*)&oa[nt*8 + 2*lr] = make_float2(o[nt][0]*il, o[nt][1]*il);
        *(float2*)&ob[nt*8 + 2*lr] = make_float2(o[nt][2]*ih, o[nt][3]*ih);
    }
}

// ---------------- fused out-gate aggregation (warp per token) ----------------
__global__ __launch_bounds__(256) void out_gate_kernel(
    const float* __restrict__ glg, const float* __restrict__ attn, float* __restrict__ agg)
{
    const int bt   = blockIdx.x * 8 + (threadIdx.x >> 5);
    const int lane = threadIdx.x & 31;
    const float* arow = attn + (size_t)bt * HD;
    const float* g    = glg + (size_t)bt * NGATE + G_GLO;

    float acc[EE][2];
#pragma unroll
    for (int e = 0; e < EE; e++) { acc[e][0] = 0.f; acc[e][1] = 0.f; }

#pragma unroll
    for (int h = 0; h < HH; h++) {
        float2 a = *(const float2*)&arow[h * DHH + 2 * lane];
        float ga[5] = { g[h*5+0], g[h*5+1], g[h*5+2], g[h*5+3], g[h*5+4] };
        int i1, i2;
        top2_of5(ga, i1, i2);
#pragma unroll
        for (int e = 0; e < EE; e++) {
            if (e == i1 || e == i2) { acc[e][0] += a.x; acc[e][1] += a.y; }
        }
    }
    float* ar = agg + (size_t)bt * (EE * DHH);
#pragma unroll
    for (int e = 0; e < EE; e++) {
        float2 r;
        r.x = __uint_as_float(f2tf32(acc[e][0]));
        r.y = __uint_as_float(f2tf32(acc[e][1]));
        *(float2*)&ar[e * DHH + 2 * lane] = r;
    }
}

// ---------------- launcher ---------------------------------------------------
extern "C" void kernel_launch(void* const* d_in, const int* in_sizes, int n_in,
                              void* d_out, int out_size)
{
    const float* x  = (const float*)d_in[0];
    const float* Wq = (const float*)d_in[1];
    const float* Wk = (const float*)d_in[2];
    const float* Ws = (const float*)d_in[3];
    const float* Wd = (const float*)d_in[4];
    const float* Wv = (const float*)d_in[5];
    const float* Wo = (const float*)d_in[6];
    float* out = (float*)d_out;

    float *xt, *Bbig, *Bg, *WoT, *proj, *glgp, *glg, *v, *attn, *agg;
    cudaGetSymbolAddress((void**)&xt,   g_xt);
    cudaGetSymbolAddress((void**)&Bbig, g_Bbig);
    cudaGetSymbolAddress((void**)&Bg,   g_Bg);
    cudaGetSymbolAddress((void**)&WoT,  g_WoT);
    cudaGetSymbolAddress((void**)&proj, g_proj);
    cudaGetSymbolAddress((void**)&glgp, g_glgp);
    cudaGetSymbolAddress((void**)&glg,  g_glg);
    cudaGetSymbolAddress((void**)&v,    g_v);
    cudaGetSymbolAddress((void**)&attn, g_at);
    cudaGetSymbolAddress((void**)&agg,  g_agg);

    // No carveout attributes (R7 lesson). Only raise max dynamic smem.
    cudaFuncSetAttribute(tf32_gemm_kernel<0, true>,
                         cudaFuncAttributeMaxDynamicSharedMemorySize, GEMM_SMEM_BYTES);
    cudaFuncSetAttribute(tf32_gemm_kernel<0, false>,
                         cudaFuncAttributeMaxDynamicSharedMemorySize, GEMM_SMEM_BYTES);
    cudaFuncSetAttribute(tf32_gemm_kernel<3, false>,
                         cudaFuncAttributeMaxDynamicSharedMemorySize, GEMM_SMEM_BYTES);
    cudaFuncSetAttribute(flash_attn_tc_kernel,
                         cudaFuncAttributeMaxDynamicSharedMemorySize, FL_SMEM);

    // Side stream + fork/join events (host objects; created at capture time,
    // not captured; no device allocations).
    cudaStream_t s2;
    cudaStreamCreateWithFlags(&s2, cudaStreamNonBlocking);
    cudaEvent_t eFork, eJoin;
    cudaEventCreateWithFlags(&eFork, cudaEventDisableTiming);
    cudaEventCreateWithFlags(&eJoin, cudaEventDisableTiming);

    // Main stream: pack_x + pack_bbig (proj GEMM inputs)
    {
        int n4 = BT * DD / 4;
        pack_x_kernel<<<(n4 + 255) / 256, 256>>>((const float4*)x, (uint4*)xt, n4);
        int nb = DD * NPROJ;
        pack_bbig_kernel<<<(nb + 255) / 256, 256>>>(Wq, Wk, Wv, (uint32_t*)Bbig);
    }

    // Fork: side stream runs the gate chain + pack_wo concurrently with proj GEMM
    cudaEventRecord(eFork, 0);
    cudaStreamWaitEvent(s2, eFork, 0);

    // --- side stream (s2): gate path -----------------------------------------
    {
        int ng = DD * NGATE;
        pack_bg_kernel<<<(ng + 255) / 256, 256, 0, s2>>>(Ws, Wd, Bg);
        tf32_gemm_kernel<3, false><<<dim3(1, BT / 128, GATE_NSPLIT), 256,
                                     GEMM_SMEM_BYTES, s2>>>(
            x, Bg, glgp, BT, NGATE, GATE_KCHUNK, DD, NGATE, NGATE,
            GATE_KCHUNK, (size_t)BT * NGATE);
        int n4 = BT * NGATE / 4;
        gate_reduce_kernel<<<(n4 + 255) / 256, 256, 0, s2>>>(
            (const float4*)glgp, (float4*)glg);
        int nw = EE * DHH * DD;
        pack_wo_kernel<<<(nw + 255) / 256, 256, 0, s2>>>(Wo, (uint32_t*)WoT, nw);
    }

    // --- main stream: q/k/xv projection (raw-bit 1x) --------------------------
    tf32_gemm_kernel<0, true><<<dim3(NPROJ / 128, BT / 128), 256, GEMM_SMEM_BYTES>>>(
        xt, Bbig, proj, BT, NPROJ, DD, DD, NPROJ, NPROJ, 0, 0);

    // Join: main stream waits for the gate chain before v_combine
    cudaEventRecord(eJoin, s2);
    cudaStreamWaitEvent(0, eJoin, 0);

    // V combine (warp per token)
    v_combine_kernel<<<BT / 8, 256>>>(glg, proj, v);

    // Tensor-core flash attention
    flash_attn_tc_kernel<<<dim3(TT / 128, BB * HH), 256, FL_SMEM>>>(proj, v, attn);

    // Output-gate aggregation (warp per token; writes tf32-rounded agg)
    out_gate_kernel<<<BT / 8, 256>>>(glg, attn, agg);

    // Output expert GEMM: raw-bit 1x  out = agg[8192,320] @ WoT[320,1024]
    tf32_gemm_kernel<0, false><<<dim3(DD / 128, BT / 128), 256, GEMM_SMEM_BYTES>>>(
        agg, WoT, out, BT, DD, EE * DHH, EE * DHH, DD, DD, 0, 0);
}

// round 14
// speedup vs baseline: 1.5889x; 1.0177x over previous
#include <cuda_runtime.h>
#include <cstdint>

#define BB   4
#define TT   2048
#define DD   1024
#define HH   8
#define DHH  64
#define EE   5
#define BT   (BB*TT)     // 8192
#define HD   (HH*DHH)    // 512
#define EDH  (EE*DHH)    // 320
#define NPROJ 1408       // [q 512 | k 512 | xv 320 | pad 64]
#define NGATE 128        // [glv 40 | glo 40 | pad 48]
#define C_Q   0
#define C_K   512
#define C_XV  1024
#define G_GLV 0
#define G_GLO 40
#define GATE_NSPLIT 8
#define GATE_KCHUNK (DD/GATE_NSPLIT)   // 128

// ---------------- scratch (device globals; no allocations allowed) ----------
__device__ float g_xt  [BT*DD];                 // x pre-rounded to tf32
__device__ float g_Bbig[DD*NPROJ];              // packed [Wq|Wk|Wv|0] tf32
__device__ float g_Bg  [DD*NGATE];              // packed [Ws|Wd|0] fp32 (3x path)
__device__ float g_WoT [EDH*DD];                // Wo pre-rounded to tf32
__device__ float g_proj[BT*NPROJ];
__device__ float g_glgp[GATE_NSPLIT*BT*NGATE];  // split-K partials
__device__ float g_glg [BT*NGATE];
__device__ float g_v   [BT*HD];
__device__ float g_at  [BT*HD];
__device__ float g_agg [BT*EDH];                // tf32-rounded by out_gate

// ---------------- helpers ----------------------------------------------------
__device__ __forceinline__ uint32_t f2tf32(float x) {
    uint32_t r;
    asm("cvt.rna.tf32.f32 %0, %1;" : "=r"(r) : "f"(x));
    return r;
}
__device__ __forceinline__ void tf32_split(float x, uint32_t& hi, uint32_t& lo) {
    hi = f2tf32(x);
    lo = f2tf32(x - __uint_as_float(hi));
}
__device__ __forceinline__ float ex2(float x) {
    float r; asm("ex2.approx.ftz.f32 %0, %1;" : "=f"(r) : "f"(x)); return r;
}
__device__ __forceinline__ void cp_async16(uint32_t s, const void* g) {
    asm volatile("cp.async.cg.shared.global [%0], [%1], 16;" :: "r"(s), "l"(g));
}
__device__ __forceinline__ void cp_commit() { asm volatile("cp.async.commit_group;"); }
__device__ __forceinline__ void cp_wait0()  { asm volatile("cp.async.wait_group 0;"); }
__device__ __forceinline__ void cp_wait1()  { asm volatile("cp.async.wait_group 1;"); }
__device__ __forceinline__ void mma_tf32(float* c, const uint32_t* a, const uint32_t* b) {
    asm volatile(
        "mma.sync.aligned.m16n8k8.row.col.f32.tf32.tf32.f32 "
        "{%0,%1,%2,%3}, {%4,%5,%6,%7}, {%8,%9}, {%0,%1,%2,%3};"
        : "+f"(c[0]), "+f"(c[1]), "+f"(c[2]), "+f"(c[3])
        : "r"(a[0]), "r"(a[1]), "r"(a[2]), "r"(a[3]), "r"(b[0]), "r"(b[1]));
}

// ---------------- pack kernels ----------------------------------------------
__global__ void pack_x_kernel(const float4* __restrict__ x, uint4* __restrict__ y, int n4) {
    int i = blockIdx.x * 256 + threadIdx.x;
    if (i >= n4) return;
    float4 v = x[i];
    uint4 o;
    o.x = f2tf32(v.x); o.y = f2tf32(v.y); o.z = f2tf32(v.z); o.w = f2tf32(v.w);
    y[i] = o;
}
__global__ void pack_bbig_kernel(const float* __restrict__ Wq, const float* __restrict__ Wk,
                                 const float* __restrict__ Wv, uint32_t* __restrict__ Bb) {
    int idx = blockIdx.x * 256 + threadIdx.x;
    if (idx >= DD * NPROJ) return;
    int d = idx / NPROJ, c = idx % NPROJ;
    float v = 0.f;
    if      (c < 512)  v = Wq[d * 512 + c];
    else if (c < 1024) v = Wk[d * 512 + c - 512];
    else if (c < 1344) {
        int cc = c - 1024;
        int e = cc >> 6, kk = cc & 63;
        v = Wv[((size_t)e * DD + d) * 64 + kk];
    }
    Bb[idx] = f2tf32(v);
}
__global__ void pack_bg_kernel(const float* __restrict__ Ws, const float* __restrict__ Wd,
                               float* __restrict__ Bg) {
    int idx = blockIdx.x * 256 + threadIdx.x;
    if (idx >= DD * NGATE) return;
    int d = idx / NGATE, c = idx % NGATE;
    float v = 0.f;
    if      (c < 40) v = Ws[d * 40 + c];
    else if (c < 80) v = Wd[d * 40 + c - 40];
    Bg[idx] = v;
}
__global__ void pack_wo_kernel(const float* __restrict__ Wo, uint32_t* __restrict__ y, int n) {
    int i = blockIdx.x * 256 + threadIdx.x;
    if (i >= n) return;
    y[i] = f2tf32(Wo[i]);
}

// ---------------- tf32 tensor-core GEMM (SPLIT: 0=raw-bits, 1=cvt, 3=3x) ----
#define SA_STRIDE 36
#define SB_STRIDE 136
#define SA_FLOATS (128*SA_STRIDE)
#define SB_FLOATS (32*SB_STRIDE)
#define GEMM_SMEM_BYTES ((2*SA_FLOATS + 2*SB_FLOATS)*4)  // 71680

template<int SPLIT, bool ROUND>
__global__ __launch_bounds__(256) void tf32_gemm_kernel(
    const float* __restrict__ A, const float* __restrict__ B, float* __restrict__ C,
    int M, int N, int K, int lda, int ldb, int ldc, int ksplit, size_t csplit)
{
    extern __shared__ float smem[];
    float* sA = smem;
    float* sB = smem + 2 * SA_FLOATS;

    {
        const int z = blockIdx.z;
        const int kbeg = z * ksplit;
        A += kbeg;
        B += (size_t)kbeg * ldb;
        C += (size_t)z * csplit;
    }

    const int tid  = threadIdx.x;
    const int warp = tid >> 5, lane = tid & 31;
    const int lq = lane >> 2, lr = lane & 3;
    const int wm = (warp & 1) * 64;
    const int wn = (warp >> 1) * 32;
    const int bm = blockIdx.y * 128;
    const int bn = blockIdx.x * 128;

    float acc[4][4][4];
#pragma unroll
    for (int i = 0; i < 4; i++)
#pragma unroll
        for (int j = 0; j < 4; j++)
#pragma unroll
            for (int v = 0; v < 4; v++) acc[i][j][v] = 0.f;

    const uint32_t sA_base = (uint32_t)__cvta_generic_to_shared(sA);
    const uint32_t sB_base = (uint32_t)__cvta_generic_to_shared(sB);

#define COPY_STAGE(buf, k0)                                                     \
    {                                                                           \
        _Pragma("unroll")                                                       \
        for (int it = 0; it < 4; it++) {                                        \
            int f = tid + it * 256;                                             \
            int ar = f >> 3, ac4 = f & 7;                                       \
            cp_async16(sA_base + ((buf) * SA_FLOATS + ar * SA_STRIDE + ac4 * 4) * 4, \
                       A + (size_t)(bm + ar) * lda + (k0) + ac4 * 4);           \
            int br = f >> 5, bc4 = f & 31;                                      \
            cp_async16(sB_base + ((buf) * SB_FLOATS + br * SB_STRIDE + bc4 * 4) * 4, \
                       B + (size_t)((k0) + br) * ldb + bn + bc4 * 4);           \
        }                                                                       \
    }

    const int nk = K >> 5;
    COPY_STAGE(0, 0);
    cp_commit();

    for (int kt = 0; kt < nk; kt++) {
        if (kt + 1 < nk) {
            COPY_STAGE((kt + 1) & 1, (kt + 1) << 5);
            cp_commit();
            cp_wait1();
        } else {
            cp_wait0();
        }
        __syncthreads();

        const float* cA = sA + (kt & 1) * SA_FLOATS;
        const float* cB = sB + (kt & 1) * SB_FLOATS;
#pragma unroll
        for (int s = 0; s < 4; s++) {
            uint32_t ah[4][4], al[4][4], bh[4][2], bl[4][2];
#pragma unroll
            for (int i = 0; i < 4; i++) {
                int base = (wm + i * 16 + lq) * SA_STRIDE + s * 8 + lr;
                if (SPLIT == 3) {
                    tf32_split(cA[base],                  ah[i][0], al[i][0]);
                    tf32_split(cA[base + 8 * SA_STRIDE],  ah[i][1], al[i][1]);
                    tf32_split(cA[base + 4],              ah[i][2], al[i][2]);
                    tf32_split(cA[base + 8*SA_STRIDE+4],  ah[i][3], al[i][3]);
                } else if (SPLIT == 1) {
                    ah[i][0] = f2tf32(cA[base]);
                    ah[i][1] = f2tf32(cA[base + 8 * SA_STRIDE]);
                    ah[i][2] = f2tf32(cA[base + 4]);
                    ah[i][3] = f2tf32(cA[base + 8*SA_STRIDE+4]);
                } else {            // SPLIT == 0: operands pre-rounded to tf32
                    ah[i][0] = __float_as_uint(cA[base]);
                    ah[i][1] = __float_as_uint(cA[base + 8 * SA_STRIDE]);
                    ah[i][2] = __float_as_uint(cA[base + 4]);
                    ah[i][3] = __float_as_uint(cA[base + 8*SA_STRIDE+4]);
                }
            }
#pragma unroll
            for (int j = 0; j < 4; j++) {
                int base = (s * 8 + lr) * SB_STRIDE + wn + j * 8 + lq;
                if (SPLIT == 3) {
                    tf32_split(cB[base],                  bh[j][0], bl[j][0]);
                    tf32_split(cB[base + 4 * SB_STRIDE],  bh[j][1], bl[j][1]);
                } else if (SPLIT == 1) {
                    bh[j][0] = f2tf32(cB[base]);
                    bh[j][1] = f2tf32(cB[base + 4 * SB_STRIDE]);
                } else {
                    bh[j][0] = __float_as_uint(cB[base]);
                    bh[j][1] = __float_as_uint(cB[base + 4 * SB_STRIDE]);
                }
            }
#pragma unroll
            for (int i = 0; i < 4; i++)
#pragma unroll
                for (int j = 0; j < 4; j++) {
                    if (SPLIT == 3) {
                        mma_tf32(acc[i][j], ah[i], bl[j]);
                        mma_tf32(acc[i][j], al[i], bh[j]);
                    }
                    mma_tf32(acc[i][j], ah[i], bh[j]);
                }
        }
        __syncthreads();
    }
#undef COPY_STAGE

#pragma unroll
    for (int i = 0; i < 4; i++) {
        int r0 = bm + wm + i * 16 + lq;
#pragma unroll
        for (int j = 0; j < 4; j++) {
            int c0 = bn + wn + j * 8 + 2 * lr;
            float v0, v1, v2, v3;
            if (ROUND) {
                v0 = __uint_as_float(f2tf32(acc[i][j][0]));
                v1 = __uint_as_float(f2tf32(acc[i][j][1]));
                v2 = __uint_as_float(f2tf32(acc[i][j][2]));
                v3 = __uint_as_float(f2tf32(acc[i][j][3]));
            } else {
                v0 = acc[i][j][0]; v1 = acc[i][j][1];
                v2 = acc[i][j][2]; v3 = acc[i][j][3];
            }
            *(float2*)&C[(size_t)r0 * ldc + c0]       = make_float2(v0, v1);
            *(float2*)&C[(size_t)(r0 + 8) * ldc + c0] = make_float2(v2, v3);
        }
    }
}

// ---------------- split-K reduce (fixed order -> deterministic) --------------
__global__ void gate_reduce_kernel(const float4* __restrict__ part, float4* __restrict__ out) {
    int i = blockIdx.x * 256 + threadIdx.x;
    if (i >= BT * NGATE / 4) return;
    const int stride = BT * NGATE / 4;
    float4 r = part[i];
#pragma unroll
    for (int p = 1; p < GATE_NSPLIT; p++) {
        float4 a = part[i + p * stride];
        r.x += a.x; r.y += a.y; r.z += a.z; r.w += a.w;
    }
    out[i] = r;
}

// ---------------- top-2 helper ----------------------------------------------
__device__ __forceinline__ void top2_of5(const float g[5], int& i1, int& i2) {
    i1 = 0;
#pragma unroll
    for (int e = 1; e < 5; e++) if (g[e] > g[i1]) i1 = e;
    i2 = (i1 == 0) ? 1 : 0;
#pragma unroll
    for (int e = 0; e < 5; e++) if (e != i1 && g[e] > g[i2]) i2 = e;
}

// ---------------- fused V combine (warp per token) ---------------------------
__global__ __launch_bounds__(256) void v_combine_kernel(
    const float* __restrict__ glg, const float* __restrict__ proj, float* __restrict__ v)
{
    const int bt   = blockIdx.x * 8 + (threadIdx.x >> 5);
    const int lane = threadIdx.x & 31;
    const float* g  = glg + (size_t)bt * NGATE + G_GLV;
    const float* xv = proj + (size_t)bt * NPROJ + C_XV;
    float* vr = v + (size_t)bt * HD;
#pragma unroll
    for (int h = 0; h < HH; h++) {
        float ga[5] = { g[h*5+0], g[h*5+1], g[h*5+2], g[h*5+3], g[h*5+4] };
        int i1, i2;
        top2_of5(ga, i1, i2);
        float w1 = 1.f / (1.f + __expf(-ga[i1]));
        float w2 = 1.f / (1.f + __expf(-ga[i2]));
        float2 x1 = *(const float2*)&xv[i1 * DHH + 2 * lane];
        float2 x2 = *(const float2*)&xv[i2 * DHH + 2 * lane];
        float2 r;
        r.x = __uint_as_float(f2tf32(w1 * x1.x + w2 * x2.x));
        r.y = __uint_as_float(f2tf32(w1 * x1.y + w2 * x2.y));
        *(float2*)&vr[h * DHH + 2 * lane] = r;
    }
}

// ---------------- tensor-core flash attention --------------------------------
#define KSTRIDE 68
#define VSTRIDE 72
#define FL_SMEM ((2*64*KSTRIDE + 2*64*VSTRIDE)*4)   // 71680

__global__ __launch_bounds__(256) void flash_attn_tc_kernel(
    const float* __restrict__ proj, const float* __restrict__ v, float* __restrict__ attn)
{
    extern __shared__ float fsm[];
    float* sK = fsm;
    float* sV = fsm + 2*64*KSTRIDE;
    const int tid  = threadIdx.x;
    const int warp = tid >> 5, lane = tid & 31;
    const int lq = lane >> 2, lr = lane & 3;
    const int h = blockIdx.y & 7, b = blockIdx.y >> 3;
    const int qbase = blockIdx.x * 128 + warp * 16;

    const uint32_t sKu = (uint32_t)__cvta_generic_to_shared(sK);
    const uint32_t sVu = (uint32_t)__cvta_generic_to_shared(sV);

    const float QS = 0.1803368801f;   // 0.125 * log2(e)
    uint32_t qa[8][4];
    {
        const float* pa = proj + (size_t)(b*TT + qbase + lq) * NPROJ + C_Q + h*64;
        const float* pb = pa + (size_t)8 * NPROJ;
#pragma unroll
        for (int kc = 0; kc < 8; kc++) {
            qa[kc][0] = f2tf32(QS * pa[kc*8 + lr]);
            qa[kc][1] = f2tf32(QS * pb[kc*8 + lr]);
            qa[kc][2] = f2tf32(QS * pa[kc*8 + lr + 4]);
            qa[kc][3] = f2tf32(QS * pb[kc*8 + lr + 4]);
        }
    }

    float o[8][4];
#pragma unroll
    for (int nt = 0; nt < 8; nt++) { o[nt][0]=o[nt][1]=o[nt][2]=o[nt][3]=0.f; }
    float m_lo = -1e30f, m_hi = -1e30f, l_lo = 0.f, l_hi = 0.f;

    const float* Kg = proj + (size_t)b*TT*NPROJ + C_K + h*64;
    const float* Vg = v    + (size_t)b*TT*HD   + h*64;

#define LOAD_TILE(buf, j0)                                                      \
    {                                                                           \
        _Pragma("unroll")                                                       \
        for (int it = 0; it < 4; it++) {                                        \
            int f = tid + it * 256;                                             \
            int krow = f >> 4, kseg = f & 15;                                   \
            cp_async16(sKu + ((buf)*64*KSTRIDE + krow*KSTRIDE + kseg*4)*4,      \
                       Kg + (size_t)((j0)+krow)*NPROJ + kseg*4);                \
            cp_async16(sVu + ((buf)*64*VSTRIDE + krow*VSTRIDE + kseg*4)*4,      \
                       Vg + (size_t)((j0)+krow)*HD + kseg*4);                   \
        }                                                                       \
    }

    LOAD_TILE(0, 0);
    cp_commit();

    for (int kt = 0; kt < TT/64; kt++) {
        if (kt + 1 < TT/64) { LOAD_TILE((kt+1)&1, (kt+1)*64); cp_commit(); cp_wait1(); }
        else cp_wait0();
        __syncthreads();

        const float* cK = sK + (kt & 1) * 64 * KSTRIDE;
        const float* cV = sV + (kt & 1) * 64 * VSTRIDE;

        float sc[8][4];
#pragma unroll
        for (int nt = 0; nt < 8; nt++) { sc[nt][0]=sc[nt][1]=sc[nt][2]=sc[nt][3]=0.f; }
#pragma unroll
        for (int kc = 0; kc < 8; kc++) {
#pragma unroll
            for (int nt = 0; nt < 8; nt++) {
                uint32_t bf[2];
                bf[0] = __float_as_uint(cK[(nt*8+lq)*KSTRIDE + kc*8 + lr]);
                bf[1] = __float_as_uint(cK[(nt*8+lq)*KSTRIDE + kc*8 + lr + 4]);
                mma_tf32(sc[nt], qa[kc], bf);
            }
        }

        float mxl = m_lo, mxh = m_hi;
#pragma unroll
        for (int nt = 0; nt < 8; nt++) {
            mxl = fmaxf(mxl, fmaxf(sc[nt][0], sc[nt][1]));
            mxh = fmaxf(mxh, fmaxf(sc[nt][2], sc[nt][3]));
        }
        mxl = fmaxf(mxl, __shfl_xor_sync(0xffffffffu, mxl, 1));
        mxl = fmaxf(mxl, __shfl_xor_sync(0xffffffffu, mxl, 2));
        mxh = fmaxf(mxh, __shfl_xor_sync(0xffffffffu, mxh, 1));
        mxh = fmaxf(mxh, __shfl_xor_sync(0xffffffffu, mxh, 2));
        float cl = ex2(m_lo - mxl), ch = ex2(m_hi - mxh);
        float sl = 0.f, sh = 0.f;
#pragma unroll
        for (int nt = 0; nt < 8; nt++) {
            sc[nt][0] = ex2(sc[nt][0] - mxl); sl += sc[nt][0];
            sc[nt][1] = ex2(sc[nt][1] - mxl); sl += sc[nt][1];
            sc[nt][2] = ex2(sc[nt][2] - mxh); sh += sc[nt][2];
            sc[nt][3] = ex2(sc[nt][3] - mxh); sh += sc[nt][3];
        }
        sl += __shfl_xor_sync(0xffffffffu, sl, 1);
        sl += __shfl_xor_sync(0xffffffffu, sl, 2);
        sh += __shfl_xor_sync(0xffffffffu, sh, 1);
        sh += __shfl_xor_sync(0xffffffffu, sh, 2);
        l_lo = l_lo * cl + sl;
        l_hi = l_hi * ch + sh;
        m_lo = mxl; m_hi = mxh;
#pragma unroll
        for (int nt = 0; nt < 8; nt++) {
            o[nt][0] *= cl; o[nt][1] *= cl;
            o[nt][2] *= ch; o[nt][3] *= ch;
        }

        const int srcA = (lane & ~3) | (lr >> 1);
        const bool odd = (lane & 1);
#pragma unroll
        for (int kc = 0; kc < 8; kc++) {
            float q0 = __shfl_sync(0xffffffffu, sc[kc][0], srcA);
            float q1 = __shfl_sync(0xffffffffu, sc[kc][1], srcA);
            float q2 = __shfl_sync(0xffffffffu, sc[kc][2], srcA);
            float q3 = __shfl_sync(0xffffffffu, sc[kc][3], srcA);
            float r0 = __shfl_sync(0xffffffffu, sc[kc][0], srcA + 2);
            float r1 = __shfl_sync(0xffffffffu, sc[kc][1], srcA + 2);
            float r2 = __shfl_sync(0xffffffffu, sc[kc][2], srcA + 2);
            float r3 = __shfl_sync(0xffffffffu, sc[kc][3], srcA + 2);
            uint32_t pa[4];
            pa[0] = f2tf32(odd ? q1 : q0);
            pa[1] = f2tf32(odd ? q3 : q2);
            pa[2] = f2tf32(odd ? r1 : r0);
            pa[3] = f2tf32(odd ? r3 : r2);
#pragma unroll
            for (int nt = 0; nt < 8; nt++) {
                uint32_t bf[2];
                bf[0] = __float_as_uint(cV[(kc*8+lr)*VSTRIDE + nt*8 + lq]);
                bf[1] = __float_as_uint(cV[(kc*8+lr+4)*VSTRIDE + nt*8 + lq]);
                mma_tf32(o[nt], pa, bf);
            }
        }
        __syncthreads();
    }
#undef LOAD_TILE

    float il = 1.f / l_lo, ih = 1.f / l_hi;
    float* oa = attn + (size_t)(b*TT + qbase + lq) * HD + h*64;
    float* ob = attn + (size_t)(b*TT + qbase + lq + 8) * HD + h*64;
#pragma unroll
    for (int nt = 0; nt < 8; nt++) {
        *(float2*)&oa[nt*8 + 2*lr] = make_float2(o[nt][0]*il, o[nt][1]*il);
        *(float2*)&ob[nt*8 + 2*lr] = make_float2(o[nt][2]*ih, o[nt][3]*ih);
    }
}

// ---------------- fused out-gate aggregation (warp per token) ----------------
__global__ __launch_bounds__(256) void out_gate_kernel(
    const float* __restrict__ glg, const float* __restrict__ attn, float* __restrict__ agg)
{
    const int bt   = blockIdx.x * 8 + (threadIdx.x >> 5);
    const int lane = threadIdx.x & 31;
    const float* arow = attn + (size_t)bt * HD;
    const float* g    = glg + (size_t)bt * NGATE + G_GLO;

    float acc[EE][2];
#pragma unroll
    for (int e = 0; e < EE; e++) { acc[e][0] = 0.f; acc[e][1] = 0.f; }

#pragma unroll
    for (int h = 0; h < HH; h++) {
        float2 a = *(const float2*)&arow[h * DHH + 2 * lane];
        float ga[5] = { g[h*5+0], g[h*5+1], g[h*5+2], g[h*5+3], g[h*5+4] };
        int i1, i2;
        top2_of5(ga, i1, i2);
#pragma unroll
        for (int e = 0; e < EE; e++) {
            if (e == i1 || e == i2) { acc[e][0] += a.x; acc[e][1] += a.y; }
        }
    }
    float* ar = agg + (size_t)bt * EDH;
#pragma unroll
    for (int e = 0; e < EE; e++) {
        float2 r;
        r.x = __uint_as_float(f2tf32(acc[e][0]));
        r.y = __uint_as_float(f2tf32(acc[e][1]));
        *(float2*)&ar[e * DHH + 2 * lane] = r;
    }
}

// ---------------- launcher ---------------------------------------------------
extern "C" void kernel_launch(void* const* d_in, const int* in_sizes, int n_in,
                              void* d_out, int out_size)
{
    const float* x  = (const float*)d_in[0];
    const float* Wq = (const float*)d_in[1];
    const float* Wk = (const float*)d_in[2];
    const float* Ws = (const float*)d_in[3];
    const float* Wd = (const float*)d_in[4];
    const float* Wv = (const float*)d_in[5];
    const float* Wo = (const float*)d_in[6];
    float* out = (float*)d_out;

    float *xt, *Bbig, *Bg, *WoT, *proj, *glgp, *glg, *v, *attn, *agg;
    cudaGetSymbolAddress((void**)&xt,   g_xt);
    cudaGetSymbolAddress((void**)&Bbig, g_Bbig);
    cudaGetSymbolAddress((void**)&Bg,   g_Bg);
    cudaGetSymbolAddress((void**)&WoT,  g_WoT);
    cudaGetSymbolAddress((void**)&proj, g_proj);
    cudaGetSymbolAddress((void**)&glgp, g_glgp);
    cudaGetSymbolAddress((void**)&glg,  g_glg);
    cudaGetSymbolAddress((void**)&v,    g_v);
    cudaGetSymbolAddress((void**)&attn, g_at);
    cudaGetSymbolAddress((void**)&agg,  g_agg);

    // No carveout attributes (R7 lesson). Only raise max dynamic smem.
    cudaFuncSetAttribute(tf32_gemm_kernel<0, true>,
                         cudaFuncAttributeMaxDynamicSharedMemorySize, GEMM_SMEM_BYTES);
    cudaFuncSetAttribute(tf32_gemm_kernel<0, false>,
                         cudaFuncAttributeMaxDynamicSharedMemorySize, GEMM_SMEM_BYTES);
    cudaFuncSetAttribute(tf32_gemm_kernel<3, false>,
                         cudaFuncAttributeMaxDynamicSharedMemorySize, GEMM_SMEM_BYTES);
    cudaFuncSetAttribute(flash_attn_tc_kernel,
                         cudaFuncAttributeMaxDynamicSharedMemorySize, FL_SMEM);

    // Streams + events (host objects; created at capture time, not captured).
    cudaStream_t s2;
    cudaStreamCreateWithFlags(&s2, cudaStreamNonBlocking);
    cudaEvent_t eFork, eProj[BB], eFl[BB];
    cudaEventCreateWithFlags(&eFork, cudaEventDisableTiming);
    for (int b = 0; b < BB; b++) {
        cudaEventCreateWithFlags(&eProj[b], cudaEventDisableTiming);
        cudaEventCreateWithFlags(&eFl[b],   cudaEventDisableTiming);
    }

    // Main stream: pack_x + pack_bbig (proj GEMM inputs)
    {
        int n4 = BT * DD / 4;
        pack_x_kernel<<<(n4 + 255) / 256, 256>>>((const float4*)x, (uint4*)xt, n4);
        int nb = DD * NPROJ;
        pack_bbig_kernel<<<(nb + 255) / 256, 256>>>(Wq, Wk, Wv, (uint32_t*)Bbig);
    }

    // Fork: side stream runs the gate chain + pack_wo concurrently with proj
    cudaEventRecord(eFork, 0);
    cudaStreamWaitEvent(s2, eFork, 0);

    // --- side stream (s2): gate path -----------------------------------------
    {
        int ng = DD * NGATE;
        pack_bg_kernel<<<(ng + 255) / 256, 256, 0, s2>>>(Ws, Wd, Bg);
        tf32_gemm_kernel<3, false><<<dim3(1, BT / 128, GATE_NSPLIT), 256,
                                     GEMM_SMEM_BYTES, s2>>>(
            x, Bg, glgp, BT, NGATE, GATE_KCHUNK, DD, NGATE, NGATE,
            GATE_KCHUNK, (size_t)BT * NGATE);
        int n4 = BT * NGATE / 4;
        gate_reduce_kernel<<<(n4 + 255) / 256, 256, 0, s2>>>(
            (const float4*)glgp, (float4*)glg);
        int nw = EDH * DD;
        pack_wo_kernel<<<(nw + 255) / 256, 256, 0, s2>>>(Wo, (uint32_t*)WoT, nw);
    }

    // --- main stream: per-batch proj GEMMs (raw-bit 1x), record per-batch evts
    for (int b = 0; b < BB; b++) {
        tf32_gemm_kernel<0, true><<<dim3(NPROJ / 128, TT / 128), 256, GEMM_SMEM_BYTES>>>(
            xt + (size_t)b * TT * DD, Bbig, proj + (size_t)b * TT * NPROJ,
            TT, NPROJ, DD, DD, NPROJ, NPROJ, 0, 0);
        cudaEventRecord(eProj[b], 0);
    }

    // --- side stream (s2): per-batch v_combine + flash, pipelined -------------
    for (int b = 0; b < BB; b++) {
        cudaStreamWaitEvent(s2, eProj[b], 0);
        v_combine_kernel<<<TT / 8, 256, 0, s2>>>(
            glg + (size_t)b * TT * NGATE, proj + (size_t)b * TT * NPROJ,
            v + (size_t)b * TT * HD);
        flash_attn_tc_kernel<<<dim3(TT / 128, HH), 256, FL_SMEM, s2>>>(
            proj + (size_t)b * TT * NPROJ, v + (size_t)b * TT * HD,
            attn + (size_t)b * TT * HD);
        cudaEventRecord(eFl[b], s2);
    }

    // --- main stream: per-batch out_gate + out GEMM as flash results land -----
    for (int b = 0; b < BB; b++) {
        cudaStreamWaitEvent(0, eFl[b], 0);
        out_gate_kernel<<<TT / 8, 256>>>(
            glg + (size_t)b * TT * NGATE, attn + (size_t)b * TT * HD,
            agg + (size_t)b * TT * EDH);
        tf32_gemm_kernel<0, false><<<dim3(DD / 128, TT / 128), 256, GEMM_SMEM_BYTES>>>(
            agg + (size_t)b * TT * EDH, WoT, out + (size_t)b * TT * DD,
            TT, DD, EDH, EDH, DD, DD, 0, 0);
    }
}

// round 15
// speedup vs baseline: 1.6095x; 1.0129x over previous
#include <cuda_runtime.h>
#include <cstdint>

#define BB   4
#define TT   2048
#define DD   1024
#define HH   8
#define DHH  64
#define EE   5
#define BT   (BB*TT)     // 8192
#define HD   (HH*DHH)    // 512
#define EDH  (EE*DHH)    // 320
#define NPROJ 1408       // [q 512 | k 512 | xv 320 | pad 64]
#define NGATE 128        // [glv 40 | glo 40 | pad 48]
#define C_Q   0
#define C_K   512
#define C_XV  1024
#define G_GLV 0
#define G_GLO 40
#define GATE_NSPLIT 8
#define GATE_KCHUNK (DD/GATE_NSPLIT)   // 128

// ---------------- scratch (device globals; no allocations allowed) ----------
__device__ float g_xt  [BT*DD];                 // x pre-rounded to tf32
__device__ float g_Bbig[DD*NPROJ];              // packed [Wq|Wk|Wv|0] tf32
__device__ float g_Bg  [DD*NGATE];              // packed [Ws|Wd|0] fp32 (3x path)
__device__ float g_WoT [EDH*DD];                // Wo pre-rounded to tf32
__device__ float g_proj[BT*NPROJ];
__device__ float g_glgp[GATE_NSPLIT*BT*NGATE];  // split-K partials
__device__ float g_glg [BT*NGATE];
__device__ float g_v   [BT*HD];
__device__ float g_at  [BT*HD];
__device__ float g_agg [BT*EDH];                // tf32-rounded by out_gate

// ---------------- helpers ----------------------------------------------------
__device__ __forceinline__ uint32_t f2tf32(float x) {
    uint32_t r;
    asm("cvt.rna.tf32.f32 %0, %1;" : "=r"(r) : "f"(x));
    return r;
}
__device__ __forceinline__ void tf32_split(float x, uint32_t& hi, uint32_t& lo) {
    hi = f2tf32(x);
    lo = f2tf32(x - __uint_as_float(hi));
}
__device__ __forceinline__ float ex2(float x) {
    float r; asm("ex2.approx.ftz.f32 %0, %1;" : "=f"(r) : "f"(x)); return r;
}
__device__ __forceinline__ void cp_async16(uint32_t s, const void* g) {
    asm volatile("cp.async.cg.shared.global [%0], [%1], 16;" :: "r"(s), "l"(g));
}
__device__ __forceinline__ void cp_commit() { asm volatile("cp.async.commit_group;"); }
__device__ __forceinline__ void cp_wait0()  { asm volatile("cp.async.wait_group 0;"); }
__device__ __forceinline__ void cp_wait1()  { asm volatile("cp.async.wait_group 1;"); }
__device__ __forceinline__ void mma_tf32(float* c, const uint32_t* a, const uint32_t* b) {
    asm volatile(
        "mma.sync.aligned.m16n8k8.row.col.f32.tf32.tf32.f32 "
        "{%0,%1,%2,%3}, {%4,%5,%6,%7}, {%8,%9}, {%0,%1,%2,%3};"
        : "+f"(c[0]), "+f"(c[1]), "+f"(c[2]), "+f"(c[3])
        : "r"(a[0]), "r"(a[1]), "r"(a[2]), "r"(a[3]), "r"(b[0]), "r"(b[1]));
}

// ---------------- pack kernels ----------------------------------------------
__global__ void pack_x_kernel(const float4* __restrict__ x, uint4* __restrict__ y, int n4) {
    int i = blockIdx.x * 256 + threadIdx.x;
    if (i >= n4) return;
    float4 v = x[i];
    uint4 o;
    o.x = f2tf32(v.x); o.y = f2tf32(v.y); o.z = f2tf32(v.z); o.w = f2tf32(v.w);
    y[i] = o;
}
__global__ void pack_bbig_kernel(const float* __restrict__ Wq, const float* __restrict__ Wk,
                                 const float* __restrict__ Wv, uint32_t* __restrict__ Bb) {
    int idx = blockIdx.x * 256 + threadIdx.x;
    if (idx >= DD * NPROJ) return;
    int d = idx / NPROJ, c = idx % NPROJ;
    float v = 0.f;
    if      (c < 512)  v = Wq[d * 512 + c];
    else if (c < 1024) v = Wk[d * 512 + c - 512];
    else if (c < 1344) {
        int cc = c - 1024;
        int e = cc >> 6, kk = cc & 63;
        v = Wv[((size_t)e * DD + d) * 64 + kk];
    }
    Bb[idx] = f2tf32(v);
}
__global__ void pack_bg_kernel(const float* __restrict__ Ws, const float* __restrict__ Wd,
                               float* __restrict__ Bg) {
    int idx = blockIdx.x * 256 + threadIdx.x;
    if (idx >= DD * NGATE) return;
    int d = idx / NGATE, c = idx % NGATE;
    float v = 0.f;
    if      (c < 40) v = Ws[d * 40 + c];
    else if (c < 80) v = Wd[d * 40 + c - 40];
    Bg[idx] = v;
}
__global__ void pack_wo_kernel(const float* __restrict__ Wo, uint32_t* __restrict__ y, int n) {
    int i = blockIdx.x * 256 + threadIdx.x;
    if (i >= n) return;
    y[i] = f2tf32(Wo[i]);
}

// ---------------- tf32 tensor-core GEMM (SPLIT: 0=raw-bits, 1=cvt, 3=3x) ----
#define SA_STRIDE 36
#define SB_STRIDE 136
#define SA_FLOATS (128*SA_STRIDE)
#define SB_FLOATS (32*SB_STRIDE)
#define GEMM_SMEM_BYTES ((2*SA_FLOATS + 2*SB_FLOATS)*4)  // 71680

template<int SPLIT, bool ROUND>
__global__ __launch_bounds__(256) void tf32_gemm_kernel(
    const float* __restrict__ A, const float* __restrict__ B, float* __restrict__ C,
    int M, int N, int K, int lda, int ldb, int ldc, int ksplit, size_t csplit)
{
    extern __shared__ float smem[];
    float* sA = smem;
    float* sB = smem + 2 * SA_FLOATS;

    {
        const int z = blockIdx.z;
        const int kbeg = z * ksplit;
        A += kbeg;
        B += (size_t)kbeg * ldb;
        C += (size_t)z * csplit;
    }

    const int tid  = threadIdx.x;
    const int warp = tid >> 5, lane = tid & 31;
    const int lq = lane >> 2, lr = lane & 3;
    const int wm = (warp & 1) * 64;
    const int wn = (warp >> 1) * 32;
    const int bm = blockIdx.y * 128;
    const int bn = blockIdx.x * 128;

    float acc[4][4][4];
#pragma unroll
    for (int i = 0; i < 4; i++)
#pragma unroll
        for (int j = 0; j < 4; j++)
#pragma unroll
            for (int v = 0; v < 4; v++) acc[i][j][v] = 0.f;

    const uint32_t sA_base = (uint32_t)__cvta_generic_to_shared(sA);
    const uint32_t sB_base = (uint32_t)__cvta_generic_to_shared(sB);

#define COPY_STAGE(buf, k0)                                                     \
    {                                                                           \
        _Pragma("unroll")                                                       \
        for (int it = 0; it < 4; it++) {                                        \
            int f = tid + it * 256;                                             \
            int ar = f >> 3, ac4 = f & 7;                                       \
            cp_async16(sA_base + ((buf) * SA_FLOATS + ar * SA_STRIDE + ac4 * 4) * 4, \
                       A + (size_t)(bm + ar) * lda + (k0) + ac4 * 4);           \
            int br = f >> 5, bc4 = f & 31;                                      \
            cp_async16(sB_base + ((buf) * SB_FLOATS + br * SB_STRIDE + bc4 * 4) * 4, \
                       B + (size_t)((k0) + br) * ldb + bn + bc4 * 4);           \
        }                                                                       \
    }

    const int nk = K >> 5;
    COPY_STAGE(0, 0);
    cp_commit();

    for (int kt = 0; kt < nk; kt++) {
        if (kt + 1 < nk) {
            COPY_STAGE((kt + 1) & 1, (kt + 1) << 5);
            cp_commit();
            cp_wait1();
        } else {
            cp_wait0();
        }
        __syncthreads();

        const float* cA = sA + (kt & 1) * SA_FLOATS;
        const float* cB = sB + (kt & 1) * SB_FLOATS;
#pragma unroll
        for (int s = 0; s < 4; s++) {
            uint32_t ah[4][4], al[4][4], bh[4][2], bl[4][2];
#pragma unroll
            for (int i = 0; i < 4; i++) {
                int base = (wm + i * 16 + lq) * SA_STRIDE + s * 8 + lr;
                if (SPLIT == 3) {
                    tf32_split(cA[base],                  ah[i][0], al[i][0]);
                    tf32_split(cA[base + 8 * SA_STRIDE],  ah[i][1], al[i][1]);
                    tf32_split(cA[base + 4],              ah[i][2], al[i][2]);
                    tf32_split(cA[base + 8*SA_STRIDE+4],  ah[i][3], al[i][3]);
                } else if (SPLIT == 1) {
                    ah[i][0] = f2tf32(cA[base]);
                    ah[i][1] = f2tf32(cA[base + 8 * SA_STRIDE]);
                    ah[i][2] = f2tf32(cA[base + 4]);
                    ah[i][3] = f2tf32(cA[base + 8*SA_STRIDE+4]);
                } else {            // SPLIT == 0: operands pre-rounded to tf32
                    ah[i][0] = __float_as_uint(cA[base]);
                    ah[i][1] = __float_as_uint(cA[base + 8 * SA_STRIDE]);
                    ah[i][2] = __float_as_uint(cA[base + 4]);
                    ah[i][3] = __float_as_uint(cA[base + 8*SA_STRIDE+4]);
                }
            }
#pragma unroll
            for (int j = 0; j < 4; j++) {
                int base = (s * 8 + lr) * SB_STRIDE + wn + j * 8 + lq;
                if (SPLIT == 3) {
                    tf32_split(cB[base],                  bh[j][0], bl[j][0]);
                    tf32_split(cB[base + 4 * SB_STRIDE],  bh[j][1], bl[j][1]);
                } else if (SPLIT == 1) {
                    bh[j][0] = f2tf32(cB[base]);
                    bh[j][1] = f2tf32(cB[base + 4 * SB_STRIDE]);
                } else {
                    bh[j][0] = __float_as_uint(cB[base]);
                    bh[j][1] = __float_as_uint(cB[base + 4 * SB_STRIDE]);
                }
            }
#pragma unroll
            for (int i = 0; i < 4; i++)
#pragma unroll
                for (int j = 0; j < 4; j++) {
                    if (SPLIT == 3) {
                        mma_tf32(acc[i][j], ah[i], bl[j]);
                        mma_tf32(acc[i][j], al[i], bh[j]);
                    }
                    mma_tf32(acc[i][j], ah[i], bh[j]);
                }
        }
        __syncthreads();
    }
#undef COPY_STAGE

#pragma unroll
    for (int i = 0; i < 4; i++) {
        int r0 = bm + wm + i * 16 + lq;
#pragma unroll
        for (int j = 0; j < 4; j++) {
            int c0 = bn + wn + j * 8 + 2 * lr;
            float v0, v1, v2, v3;
            if (ROUND) {
                v0 = __uint_as_float(f2tf32(acc[i][j][0]));
                v1 = __uint_as_float(f2tf32(acc[i][j][1]));
                v2 = __uint_as_float(f2tf32(acc[i][j][2]));
                v3 = __uint_as_float(f2tf32(acc[i][j][3]));
            } else {
                v0 = acc[i][j][0]; v1 = acc[i][j][1];
                v2 = acc[i][j][2]; v3 = acc[i][j][3];
            }
            *(float2*)&C[(size_t)r0 * ldc + c0]       = make_float2(v0, v1);
            *(float2*)&C[(size_t)(r0 + 8) * ldc + c0] = make_float2(v2, v3);
        }
    }
}

// ---------------- split-K reduce (fixed order -> deterministic) --------------
__global__ void gate_reduce_kernel(const float4* __restrict__ part, float4* __restrict__ out) {
    int i = blockIdx.x * 256 + threadIdx.x;
    if (i >= BT * NGATE / 4) return;
    const int stride = BT * NGATE / 4;
    float4 r = part[i];
#pragma unroll
    for (int p = 1; p < GATE_NSPLIT; p++) {
        float4 a = part[i + p * stride];
        r.x += a.x; r.y += a.y; r.z += a.z; r.w += a.w;
    }
    out[i] = r;
}

// ---------------- top-2 helper ----------------------------------------------
__device__ __forceinline__ void top2_of5(const float g[5], int& i1, int& i2) {
    i1 = 0;
#pragma unroll
    for (int e = 1; e < 5; e++) if (g[e] > g[i1]) i1 = e;
    i2 = (i1 == 0) ? 1 : 0;
#pragma unroll
    for (int e = 0; e < 5; e++) if (e != i1 && g[e] > g[i2]) i2 = e;
}

// ---------------- fused V combine (warp per token) ---------------------------
__global__ __launch_bounds__(256) void v_combine_kernel(
    const float* __restrict__ glg, const float* __restrict__ proj, float* __restrict__ v)
{
    const int bt   = blockIdx.x * 8 + (threadIdx.x >> 5);
    const int lane = threadIdx.x & 31;
    const float* g  = glg + (size_t)bt * NGATE + G_GLV;
    const float* xv = proj + (size_t)bt * NPROJ + C_XV;
    float* vr = v + (size_t)bt * HD;
#pragma unroll
    for (int h = 0; h < HH; h++) {
        float ga[5] = { g[h*5+0], g[h*5+1], g[h*5+2], g[h*5+3], g[h*5+4] };
        int i1, i2;
        top2_of5(ga, i1, i2);
        float w1 = 1.f / (1.f + __expf(-ga[i1]));
        float w2 = 1.f / (1.f + __expf(-ga[i2]));
        float2 x1 = *(const float2*)&xv[i1 * DHH + 2 * lane];
        float2 x2 = *(const float2*)&xv[i2 * DHH + 2 * lane];
        float2 r;
        r.x = __uint_as_float(f2tf32(w1 * x1.x + w2 * x2.x));
        r.y = __uint_as_float(f2tf32(w1 * x1.y + w2 * x2.y));
        *(float2*)&vr[h * DHH + 2 * lane] = r;
    }
}

// ---------------- tensor-core flash attention (Q in smem, 2 CTAs/SM) ---------
#define KSTRIDE 68
#define VSTRIDE 72
#define QSTRIDE 68
#define FL_SMEM ((2*64*KSTRIDE + 2*64*VSTRIDE + 128*QSTRIDE)*4)   // 106496

__global__ __launch_bounds__(256, 2) void flash_attn_tc_kernel(
    const float* __restrict__ proj, const float* __restrict__ v, float* __restrict__ attn)
{
    extern __shared__ float fsm[];
    float* sK = fsm;
    float* sV = fsm + 2*64*KSTRIDE;
    float* sQ = fsm + 2*64*KSTRIDE + 2*64*VSTRIDE;
    const int tid  = threadIdx.x;
    const int warp = tid >> 5, lane = tid & 31;
    const int lq = lane >> 2, lr = lane & 3;
    const int h = blockIdx.y & 7, b = blockIdx.y >> 3;
    const int qblock = blockIdx.x * 128;

    const uint32_t sKu = (uint32_t)__cvta_generic_to_shared(sK);
    const uint32_t sVu = (uint32_t)__cvta_generic_to_shared(sV);

    const float* Kg = proj + (size_t)b*TT*NPROJ + C_K + h*64;
    const float* Vg = v    + (size_t)b*TT*HD   + h*64;

#define LOAD_TILE(buf, j0)                                                      \
    {                                                                           \
        _Pragma("unroll")                                                       \
        for (int it = 0; it < 4; it++) {                                        \
            int f = tid + it * 256;                                             \
            int krow = f >> 4, kseg = f & 15;                                   \
            cp_async16(sKu + ((buf)*64*KSTRIDE + krow*KSTRIDE + kseg*4)*4,      \
                       Kg + (size_t)((j0)+krow)*NPROJ + kseg*4);                \
            cp_async16(sVu + ((buf)*64*VSTRIDE + krow*VSTRIDE + kseg*4)*4,      \
                       Vg + (size_t)((j0)+krow)*HD + kseg*4);                   \
        }                                                                       \
    }

    LOAD_TILE(0, 0);
    cp_commit();

    // Fill Q tile into smem: 128 rows x 64 cols, pre-scaled + tf32-rounded.
    {
        const float QS = 0.1803368801f;   // 0.125 * log2(e)
        const float* Qg = proj + (size_t)(b*TT + qblock) * NPROJ + C_Q + h*64;
        for (int i = tid; i < 128*64; i += 256) {
            int r = i >> 6, c = i & 63;
            sQ[r*QSTRIDE + c] = __uint_as_float(f2tf32(QS * Qg[(size_t)r*NPROJ + c]));
        }
    }

    float o[8][4];
#pragma unroll
    for (int nt = 0; nt < 8; nt++) { o[nt][0]=o[nt][1]=o[nt][2]=o[nt][3]=0.f; }
    float m_lo = -1e30f, m_hi = -1e30f, l_lo = 0.f, l_hi = 0.f;

    const int qrow = warp * 16 + lq;

    for (int kt = 0; kt < TT/64; kt++) {
        if (kt + 1 < TT/64) { LOAD_TILE((kt+1)&1, (kt+1)*64); cp_commit(); cp_wait1(); }
        else cp_wait0();
        __syncthreads();   // first iteration: also publishes the Q fill

        const float* cK = sK + (kt & 1) * 64 * KSTRIDE;
        const float* cV = sV + (kt & 1) * 64 * VSTRIDE;

        float sc[8][4];
#pragma unroll
        for (int nt = 0; nt < 8; nt++) { sc[nt][0]=sc[nt][1]=sc[nt][2]=sc[nt][3]=0.f; }
#pragma unroll
        for (int kc = 0; kc < 8; kc++) {
            uint32_t qa[4];
            {
                int qb = qrow * QSTRIDE + kc*8 + lr;
                qa[0] = __float_as_uint(sQ[qb]);
                qa[1] = __float_as_uint(sQ[qb + 8*QSTRIDE]);
                qa[2] = __float_as_uint(sQ[qb + 4]);
                qa[3] = __float_as_uint(sQ[qb + 8*QSTRIDE + 4]);
            }
#pragma unroll
            for (int nt = 0; nt < 8; nt++) {
                uint32_t bf[2];
                bf[0] = __float_as_uint(cK[(nt*8+lq)*KSTRIDE + kc*8 + lr]);
                bf[1] = __float_as_uint(cK[(nt*8+lq)*KSTRIDE + kc*8 + lr + 4]);
                mma_tf32(sc[nt], qa, bf);
            }
        }

        float mxl = m_lo, mxh = m_hi;
#pragma unroll
        for (int nt = 0; nt < 8; nt++) {
            mxl = fmaxf(mxl, fmaxf(sc[nt][0], sc[nt][1]));
            mxh = fmaxf(mxh, fmaxf(sc[nt][2], sc[nt][3]));
        }
        mxl = fmaxf(mxl, __shfl_xor_sync(0xffffffffu, mxl, 1));
        mxl = fmaxf(mxl, __shfl_xor_sync(0xffffffffu, mxl, 2));
        mxh = fmaxf(mxh, __shfl_xor_sync(0xffffffffu, mxh, 1));
        mxh = fmaxf(mxh, __shfl_xor_sync(0xffffffffu, mxh, 2));
        float cl = ex2(m_lo - mxl), ch = ex2(m_hi - mxh);
        float sl = 0.f, sh = 0.f;
#pragma unroll
        for (int nt = 0; nt < 8; nt++) {
            sc[nt][0] = ex2(sc[nt][0] - mxl); sl += sc[nt][0];
            sc[nt][1] = ex2(sc[nt][1] - mxl); sl += sc[nt][1];
            sc[nt][2] = ex2(sc[nt][2] - mxh); sh += sc[nt][2];
            sc[nt][3] = ex2(sc[nt][3] - mxh); sh += sc[nt][3];
        }
        sl += __shfl_xor_sync(0xffffffffu, sl, 1);
        sl += __shfl_xor_sync(0xffffffffu, sl, 2);
        sh += __shfl_xor_sync(0xffffffffu, sh, 1);
        sh += __shfl_xor_sync(0xffffffffu, sh, 2);
        l_lo = l_lo * cl + sl;
        l_hi = l_hi * ch + sh;
        m_lo = mxl; m_hi = mxh;
#pragma unroll
        for (int nt = 0; nt < 8; nt++) {
            o[nt][0] *= cl; o[nt][1] *= cl;
            o[nt][2] *= ch; o[nt][3] *= ch;
        }

        const int srcA = (lane & ~3) | (lr >> 1);
        const bool odd = (lane & 1);
#pragma unroll
        for (int kc = 0; kc < 8; kc++) {
            float q0 = __shfl_sync(0xffffffffu, sc[kc][0], srcA);
            float q1 = __shfl_sync(0xffffffffu, sc[kc][1], srcA);
            float q2 = __shfl_sync(0xffffffffu, sc[kc][2], srcA);
            float q3 = __shfl_sync(0xffffffffu, sc[kc][3], srcA);
            float r0 = __shfl_sync(0xffffffffu, sc[kc][0], srcA + 2);
            float r1 = __shfl_sync(0xffffffffu, sc[kc][1], srcA + 2);
            float r2 = __shfl_sync(0xffffffffu, sc[kc][2], srcA + 2);
            float r3 = __shfl_sync(0xffffffffu, sc[kc][3], srcA + 2);
            uint32_t pa[4];
            pa[0] = f2tf32(odd ? q1 : q0);
            pa[1] = f2tf32(odd ? q3 : q2);
            pa[2] = f2tf32(odd ? r1 : r0);
            pa[3] = f2tf32(odd ? r3 : r2);
#pragma unroll
            for (int nt = 0; nt < 8; nt++) {
                uint32_t bf[2];
                bf[0] = __float_as_uint(cV[(kc*8+lr)*VSTRIDE + nt*8 + lq]);
                bf[1] = __float_as_uint(cV[(kc*8+lr+4)*VSTRIDE + nt*8 + lq]);
                mma_tf32(o[nt], pa, bf);
            }
        }
        __syncthreads();
    }
#undef LOAD_TILE

    float il = 1.f / l_lo, ih = 1.f / l_hi;
    float* oa = attn + (size_t)(b*TT + qblock + warp*16 + lq) * HD + h*64;
    float* ob = oa + (size_t)8 * HD;
#pragma unroll
    for (int nt = 0; nt < 8; nt++) {
        *(float2*)&oa[nt*8 + 2*lr] = make_float2(o[nt][0]*il, o[nt][1]*il);
        *(float2*)&ob[nt*8 + 2*lr] = make_float2(o[nt][2]*ih, o[nt][3]*ih);
    }
}

// ---------------- fused out-gate aggregation (warp per token) ----------------
__global__ __launch_bounds__(256) void out_gate_kernel(
    const float* __restrict__ glg, const float* __restrict__ attn, float* __restrict__ agg)
{
    const int bt   = blockIdx.x * 8 + (threadIdx.x >> 5);
    const int lane = threadIdx.x & 31;
    const float* arow = attn + (size_t)bt * HD;
    const float* g    = glg + (size_t)bt * NGATE + G_GLO;

    float acc[EE][2];
#pragma unroll
    for (int e = 0; e < EE; e++) { acc[e][0] = 0.f; acc[e][1] = 0.f; }

#pragma unroll
    for (int h = 0; h < HH; h++) {
        float2 a = *(const float2*)&arow[h * DHH + 2 * lane];
        float ga[5] = { g[h*5+0], g[h*5+1], g[h*5+2], g[h*5+3], g[h*5+4] };
        int i1, i2;
        top2_of5(ga, i1, i2);
#pragma unroll
        for (int e = 0; e < EE; e++) {
            if (e == i1 || e == i2) { acc[e][0] += a.x; acc[e][1] += a.y; }
        }
    }
    float* ar = agg + (size_t)bt * EDH;
#pragma unroll
    for (int e = 0; e < EE; e++) {
        float2 r;
        r.x = __uint_as_float(f2tf32(acc[e][0]));
        r.y = __uint_as_float(f2tf32(acc[e][1]));
        *(float2*)&ar[e * DHH + 2 * lane] = r;
    }
}

// ---------------- launcher ---------------------------------------------------
extern "C" void kernel_launch(void* const* d_in, const int* in_sizes, int n_in,
                              void* d_out, int out_size)
{
    const float* x  = (const float*)d_in[0];
    const float* Wq = (const float*)d_in[1];
    const float* Wk = (const float*)d_in[2];
    const float* Ws = (const float*)d_in[3];
    const float* Wd = (const float*)d_in[4];
    const float* Wv = (const float*)d_in[5];
    const float* Wo = (const float*)d_in[6];
    float* out = (float*)d_out;

    float *xt, *Bbig, *Bg, *WoT, *proj, *glgp, *glg, *v, *attn, *agg;
    cudaGetSymbolAddress((void**)&xt,   g_xt);
    cudaGetSymbolAddress((void**)&Bbig, g_Bbig);
    cudaGetSymbolAddress((void**)&Bg,   g_Bg);
    cudaGetSymbolAddress((void**)&WoT,  g_WoT);
    cudaGetSymbolAddress((void**)&proj, g_proj);
    cudaGetSymbolAddress((void**)&glgp, g_glgp);
    cudaGetSymbolAddress((void**)&glg,  g_glg);
    cudaGetSymbolAddress((void**)&v,    g_v);
    cudaGetSymbolAddress((void**)&attn, g_at);
    cudaGetSymbolAddress((void**)&agg,  g_agg);

    // No carveout attributes (R7 lesson). Only raise max dynamic smem.
    cudaFuncSetAttribute(tf32_gemm_kernel<0, true>,
                         cudaFuncAttributeMaxDynamicSharedMemorySize, GEMM_SMEM_BYTES);
    cudaFuncSetAttribute(tf32_gemm_kernel<0, false>,
                         cudaFuncAttributeMaxDynamicSharedMemorySize, GEMM_SMEM_BYTES);
    cudaFuncSetAttribute(tf32_gemm_kernel<3, false>,
                         cudaFuncAttributeMaxDynamicSharedMemorySize, GEMM_SMEM_BYTES);
    cudaFuncSetAttribute(flash_attn_tc_kernel,
                         cudaFuncAttributeMaxDynamicSharedMemorySize, FL_SMEM);

    // Side stream + fork/join events (host objects; not captured; no dev alloc)
    cudaStream_t s2;
    cudaStreamCreateWithFlags(&s2, cudaStreamNonBlocking);
    cudaEvent_t eFork, eJoin;
    cudaEventCreateWithFlags(&eFork, cudaEventDisableTiming);
    cudaEventCreateWithFlags(&eJoin, cudaEventDisableTiming);

    // Main stream: pack_x + pack_bbig (proj GEMM inputs)
    {
        int n4 = BT * DD / 4;
        pack_x_kernel<<<(n4 + 255) / 256, 256>>>((const float4*)x, (uint4*)xt, n4);
        int nb = DD * NPROJ;
        pack_bbig_kernel<<<(nb + 255) / 256, 256>>>(Wq, Wk, Wv, (uint32_t*)Bbig);
    }

    // Fork: side stream runs the gate chain + pack_wo concurrently with proj
    cudaEventRecord(eFork, 0);
    cudaStreamWaitEvent(s2, eFork, 0);

    // --- side stream (s2): gate path -----------------------------------------
    {
        int ng = DD * NGATE;
        pack_bg_kernel<<<(ng + 255) / 256, 256, 0, s2>>>(Ws, Wd, Bg);
        tf32_gemm_kernel<3, false><<<dim3(1, BT / 128, GATE_NSPLIT), 256,
                                     GEMM_SMEM_BYTES, s2>>>(
            x, Bg, glgp, BT, NGATE, GATE_KCHUNK, DD, NGATE, NGATE,
            GATE_KCHUNK, (size_t)BT * NGATE);
        int n4 = BT * NGATE / 4;
        gate_reduce_kernel<<<(n4 + 255) / 256, 256, 0, s2>>>(
            (const float4*)glgp, (float4*)glg);
        int nw = EDH * DD;
        pack_wo_kernel<<<(nw + 255) / 256, 256, 0, s2>>>(Wo, (uint32_t*)WoT, nw);
    }

    // --- main stream: q/k/xv projection (raw-bit 1x, single launch) -----------
    tf32_gemm_kernel<0, true><<<dim3(NPROJ / 128, BT / 128), 256, GEMM_SMEM_BYTES>>>(
        xt, Bbig, proj, BT, NPROJ, DD, DD, NPROJ, NPROJ, 0, 0);

    // Join: main stream waits for the gate chain before v_combine
    cudaEventRecord(eJoin, s2);
    cudaStreamWaitEvent(0, eJoin, 0);

    // V combine (warp per token)
    v_combine_kernel<<<BT / 8, 256>>>(glg, proj, v);

    // Tensor-core flash attention (single 512-CTA launch -> 2 CTAs/SM)
    flash_attn_tc_kernel<<<dim3(TT / 128, BB * HH), 256, FL_SMEM>>>(proj, v, attn);

    // Output-gate aggregation (warp per token; writes tf32-rounded agg)
    out_gate_kernel<<<BT / 8, 256>>>(glg, attn, agg);

    // Output expert GEMM: raw-bit 1x  out = agg[8192,320] @ WoT[320,1024]
    tf32_gemm_kernel<0, false><<<dim3(DD / 128, BT / 128), 256, GEMM_SMEM_BYTES>>>(
        agg, WoT, out, BT, DD, EDH, EDH, DD, DD, 0, 0);
}